// round 1
// baseline (speedup 1.0000x reference)
#include <cuda_runtime.h>
#include <math.h>
#include <stdint.h>

#define N0C 30000
#define N1C 90000
#define N2C 60000
#define NTOT (N0C + N1C + N2C)   // 180000
#define DIN  256
#define DOUT 128
#define HEADS 4

// ---------------- scratch (device globals; no runtime allocation) ------------
__device__ __align__(128) float g_Y  [(size_t)HEADS * NTOT * DOUT];      // relu(X@W1+b1), all levels concat
__device__ __align__(128) float g_a1 [HEADS * N0C];                      // attention source term
__device__ __align__(128) float g_a2 [HEADS * NTOT];                     // attention target term (all levels)
__device__ __align__(128) float g_agg[(size_t)HEADS * 3 * N0C * DOUT];   // segment sums per head/level

// ---------------- GEMM 1: Y = relu(X @ W1[h] + b1[h]) ------------------------
// Block: 128(M) x 128(N) tile, K-step 16, 256 threads, 8x8 microtile.
__global__ __launch_bounds__(256) void gemm1_kernel(
    const float* __restrict__ X, int M,
    const float* __restrict__ W1, const float* __restrict__ b1,
    int rowOffset)
{
    const int h  = blockIdx.y;
    const int m0 = blockIdx.x * 128;
    const float* W = W1 + (size_t)h * DIN * DOUT;

    __shared__ float As[16][128];   // As[k][m]
    __shared__ float Bs[16][128];   // Bs[k][n]

    const int tid = threadIdx.x;
    const int ty = tid >> 4;        // 0..15 -> rows ty*8..
    const int tx = tid & 15;        // 0..15 -> cols tx*8..

    float acc[8][8];
#pragma unroll
    for (int i = 0; i < 8; i++)
#pragma unroll
        for (int j = 0; j < 8; j++) acc[i][j] = 0.f;

    for (int k0 = 0; k0 < DIN; k0 += 16) {
        // load A tile (128 x 16), transposed into As[k][m]
#pragma unroll
        for (int i = 0; i < 2; i++) {
            int f  = tid * 2 + i;        // 0..511 float4s
            int r  = f >> 2;             // row within tile
            int c4 = f & 3;              // which float4 of the 16 k's
            int row = m0 + r;
            float4 v = make_float4(0.f, 0.f, 0.f, 0.f);
            if (row < M)
                v = *reinterpret_cast<const float4*>(X + (size_t)row * DIN + k0 + c4 * 4);
            As[c4 * 4 + 0][r] = v.x;
            As[c4 * 4 + 1][r] = v.y;
            As[c4 * 4 + 2][r] = v.z;
            As[c4 * 4 + 3][r] = v.w;
        }
        // load B tile (16 x 128)
#pragma unroll
        for (int i = 0; i < 2; i++) {
            int f  = tid * 2 + i;
            int r  = f >> 5;             // 0..15
            int c4 = f & 31;
            float4 v = *reinterpret_cast<const float4*>(W + (size_t)(k0 + r) * DOUT + c4 * 4);
            *reinterpret_cast<float4*>(&Bs[r][c4 * 4]) = v;
        }
        __syncthreads();

#pragma unroll
        for (int k = 0; k < 16; k++) {
            float4 a0 = *reinterpret_cast<const float4*>(&As[k][ty * 8]);
            float4 a1r = *reinterpret_cast<const float4*>(&As[k][ty * 8 + 4]);
            float4 b0 = *reinterpret_cast<const float4*>(&Bs[k][tx * 8]);
            float4 b1r = *reinterpret_cast<const float4*>(&Bs[k][tx * 8 + 4]);
            float a[8] = {a0.x, a0.y, a0.z, a0.w, a1r.x, a1r.y, a1r.z, a1r.w};
            float b[8] = {b0.x, b0.y, b0.z, b0.w, b1r.x, b1r.y, b1r.z, b1r.w};
#pragma unroll
            for (int i = 0; i < 8; i++)
#pragma unroll
                for (int j = 0; j < 8; j++) acc[i][j] += a[i] * b[j];
        }
        __syncthreads();
    }

    // epilogue: + bias, relu, store into g_Y
#pragma unroll
    for (int i = 0; i < 8; i++) {
        int row = m0 + ty * 8 + i;
        if (row >= M) continue;
        float* dst = g_Y + ((size_t)h * NTOT + rowOffset + row) * DOUT;
        float v[8];
#pragma unroll
        for (int j = 0; j < 8; j++) {
            float t = acc[i][j] + b1[h * DOUT + tx * 8 + j];
            v[j] = t > 0.f ? t : 0.f;
        }
        *reinterpret_cast<float4*>(dst + tx * 8)     = make_float4(v[0], v[1], v[2], v[3]);
        *reinterpret_cast<float4*>(dst + tx * 8 + 4) = make_float4(v[4], v[5], v[6], v[7]);
    }
}

// ---------------- a1 / a2 GEMVs ----------------------------------------------
// one warp per (head, row): dot(Y[h][r], a2w[h]) + a2b ; and a1 for r < N0
__global__ __launch_bounds__(256) void a12_kernel(
    const float* __restrict__ a1w, const float* __restrict__ a1b,
    const float* __restrict__ a2w, const float* __restrict__ a2b)
{
    int w = blockIdx.x * 8 + (threadIdx.x >> 5);
    if (w >= HEADS * NTOT) return;
    int lane = threadIdx.x & 31;
    int h = w / NTOT;
    int r = w - h * NTOT;

    const float4* y = reinterpret_cast<const float4*>(g_Y + ((size_t)h * NTOT + r) * DOUT);
    float4 v  = y[lane];
    float4 w2 = reinterpret_cast<const float4*>(a2w + h * DOUT)[lane];
    float s2 = v.x * w2.x + v.y * w2.y + v.z * w2.z + v.w * w2.w;

    float s1 = 0.f;
    bool doA1 = (r < N0C);
    if (doA1) {
        float4 w1v = reinterpret_cast<const float4*>(a1w + h * DOUT)[lane];
        s1 = v.x * w1v.x + v.y * w1v.y + v.z * w1v.z + v.w * w1v.w;
    }
#pragma unroll
    for (int off = 16; off > 0; off >>= 1) {
        s2 += __shfl_xor_sync(0xffffffff, s2, off);
        s1 += __shfl_xor_sync(0xffffffff, s1, off);
    }
    if (lane == 0) {
        g_a2[h * NTOT + r] = s2 + a2b[h];
        if (doA1) g_a1[h * N0C + r] = s1 + a1b[h];
    }
}

// ---------------- zero the aggregation buffers -------------------------------
__global__ void zero_agg_kernel()
{
    const size_t n4 = (size_t)HEADS * 3 * N0C * DOUT / 4;   // 11,520,000 float4
    size_t i = (size_t)blockIdx.x * blockDim.x + threadIdx.x;
    if (i < n4)
        reinterpret_cast<float4*>(g_agg)[i] = make_float4(0.f, 0.f, 0.f, 0.f);
}

// ---------------- attention scatter ------------------------------------------
// warp per edge; lane handles one float4 of the 128-wide message; vectorized red.
__global__ __launch_bounds__(256) void edge_kernel(
    const int* __restrict__ rows, const int* __restrict__ cols,
    int nnz, int colOffset, int level)
{
    int w = blockIdx.x * 8 + (threadIdx.x >> 5);
    if (w >= nnz) return;
    const int h = blockIdx.y;
    const int lane = threadIdx.x & 31;

    int r = __ldg(rows + w);
    int c = __ldg(cols + w);

    float av  = g_a1[h * N0C + r] + g_a2[h * NTOT + colOffset + c];
    float att = 1.f / (1.f + expf(-av));

    const float4* y = reinterpret_cast<const float4*>(
        g_Y + ((size_t)h * NTOT + colOffset + c) * DOUT);
    float4 v = y[lane];
    v.x *= att; v.y *= att; v.z *= att; v.w *= att;

    float* dst = g_agg + (((size_t)h * 3 + level) * N0C + r) * DOUT + lane * 4;
    asm volatile("red.global.add.v4.f32 [%0], {%1,%2,%3,%4};"
                 :: "l"(dst), "f"(v.x), "f"(v.y), "f"(v.z), "f"(v.w)
                 : "memory");
}

// ---------------- GEMM 2: out = mean_h( cat_h @ Wagg[h] + bagg[h] ) ----------
// cat_h = [Y0 | agg0 | agg1 | agg2], K = 4 heads * 512, accumulated in one acc.
__global__ __launch_bounds__(256) void gemm2_kernel(
    const float* __restrict__ Wagg, const float* __restrict__ bagg,
    float* __restrict__ out)
{
    const int m0 = blockIdx.x * 128;

    __shared__ float As[16][128];
    __shared__ float Bs[16][128];

    const int tid = threadIdx.x;
    const int ty = tid >> 4;
    const int tx = tid & 15;

    float acc[8][8];
#pragma unroll
    for (int i = 0; i < 8; i++)
#pragma unroll
        for (int j = 0; j < 8; j++) acc[i][j] = 0.f;

    for (int h = 0; h < HEADS; h++) {
        const float* Wh = Wagg + (size_t)h * 4 * DOUT * DOUT;   // [512,128]
        for (int part = 0; part < 4; part++) {
            const float* src = (part == 0)
                ? (g_Y + (size_t)h * NTOT * DOUT)
                : (g_agg + (((size_t)h * 3 + (part - 1)) * N0C) * DOUT);
            const float* Wp = Wh + (size_t)part * DOUT * DOUT;

            for (int k0 = 0; k0 < DOUT; k0 += 16) {
                // A tile from src (stride 128 floats per row)
#pragma unroll
                for (int i = 0; i < 2; i++) {
                    int f  = tid * 2 + i;
                    int r  = f >> 2;
                    int c4 = f & 3;
                    int row = m0 + r;
                    float4 v = make_float4(0.f, 0.f, 0.f, 0.f);
                    if (row < N0C)
                        v = *reinterpret_cast<const float4*>(src + (size_t)row * DOUT + k0 + c4 * 4);
                    As[c4 * 4 + 0][r] = v.x;
                    As[c4 * 4 + 1][r] = v.y;
                    As[c4 * 4 + 2][r] = v.z;
                    As[c4 * 4 + 3][r] = v.w;
                }
                // B tile
#pragma unroll
                for (int i = 0; i < 2; i++) {
                    int f  = tid * 2 + i;
                    int r  = f >> 5;
                    int c4 = f & 31;
                    float4 v = *reinterpret_cast<const float4*>(Wp + (size_t)(k0 + r) * DOUT + c4 * 4);
                    *reinterpret_cast<float4*>(&Bs[r][c4 * 4]) = v;
                }
                __syncthreads();

#pragma unroll
                for (int k = 0; k < 16; k++) {
                    float4 a0 = *reinterpret_cast<const float4*>(&As[k][ty * 8]);
                    float4 a1r = *reinterpret_cast<const float4*>(&As[k][ty * 8 + 4]);
                    float4 b0 = *reinterpret_cast<const float4*>(&Bs[k][tx * 8]);
                    float4 b1r = *reinterpret_cast<const float4*>(&Bs[k][tx * 8 + 4]);
                    float a[8] = {a0.x, a0.y, a0.z, a0.w, a1r.x, a1r.y, a1r.z, a1r.w};
                    float b[8] = {b0.x, b0.y, b0.z, b0.w, b1r.x, b1r.y, b1r.z, b1r.w};
#pragma unroll
                    for (int i = 0; i < 8; i++)
#pragma unroll
                        for (int j = 0; j < 8; j++) acc[i][j] += a[i] * b[j];
                }
                __syncthreads();
            }
        }
    }

    // epilogue: mean over heads (x0.25) + mean bias
#pragma unroll
    for (int i = 0; i < 8; i++) {
        int row = m0 + ty * 8 + i;
        if (row >= N0C) continue;
        float v[8];
#pragma unroll
        for (int j = 0; j < 8; j++) {
            int n = tx * 8 + j;
            float bsum = bagg[0 * DOUT + n] + bagg[1 * DOUT + n]
                       + bagg[2 * DOUT + n] + bagg[3 * DOUT + n];
            v[j] = 0.25f * (acc[i][j] + bsum);
        }
        float* dst = out + (size_t)row * DOUT;
        *reinterpret_cast<float4*>(dst + tx * 8)     = make_float4(v[0], v[1], v[2], v[3]);
        *reinterpret_cast<float4*>(dst + tx * 8 + 4) = make_float4(v[4], v[5], v[6], v[7]);
    }
}

// ---------------- launcher ---------------------------------------------------
extern "C" void kernel_launch(void* const* d_in, const int* in_sizes, int n_in,
                              void* d_out, int out_size)
{
    const float* x0    = (const float*)d_in[0];
    const float* x1    = (const float*)d_in[1];
    const float* x2    = (const float*)d_in[2];
    const int*   rows0 = (const int*)  d_in[3];
    const int*   cols0 = (const int*)  d_in[4];
    const int*   rows1 = (const int*)  d_in[5];
    const int*   cols1 = (const int*)  d_in[6];
    const int*   rows2 = (const int*)  d_in[7];
    const int*   cols2 = (const int*)  d_in[8];
    const float* W1    = (const float*)d_in[9];
    const float* b1    = (const float*)d_in[10];
    const float* a1w   = (const float*)d_in[11];
    const float* a1b   = (const float*)d_in[12];
    const float* a2w   = (const float*)d_in[13];
    const float* a2b   = (const float*)d_in[14];
    const float* Wagg  = (const float*)d_in[15];
    const float* bagg  = (const float*)d_in[16];
    float* out = (float*)d_out;

    const int nnz0 = in_sizes[3];
    const int nnz1 = in_sizes[5];
    const int nnz2 = in_sizes[7];

    // 1) shared linear + relu for all three simplex levels
    gemm1_kernel<<<dim3((N0C + 127) / 128, HEADS), 256>>>(x0, N0C, W1, b1, 0);
    gemm1_kernel<<<dim3((N1C + 127) / 128, HEADS), 256>>>(x1, N1C, W1, b1, N0C);
    gemm1_kernel<<<dim3((N2C + 127) / 128, HEADS), 256>>>(x2, N2C, W1, b1, N0C + N1C);

    // 2) attention scalar terms
    a12_kernel<<<(HEADS * NTOT + 7) / 8, 256>>>(a1w, a1b, a2w, a2b);

    // 3) zero aggregation buffers
    zero_agg_kernel<<<(11520000 + 255) / 256, 256>>>();

    // 4) attention-weighted scatter for each incidence
    edge_kernel<<<dim3((nnz0 + 7) / 8, HEADS), 256>>>(rows0, cols0, nnz0, 0, 0);
    edge_kernel<<<dim3((nnz1 + 7) / 8, HEADS), 256>>>(rows1, cols1, nnz1, N0C, 1);
    edge_kernel<<<dim3((nnz2 + 7) / 8, HEADS), 256>>>(rows2, cols2, nnz2, N0C + N1C, 2);

    // 5) concat + output projection + head mean
    gemm2_kernel<<<(N0C + 127) / 128, 256>>>(Wagg, bagg, out);
}

// round 4
// speedup vs baseline: 1.3900x; 1.3900x over previous
#include <cuda_runtime.h>
#include <cuda_bf16.h>
#include <math.h>
#include <stdint.h>

#define N0C 30000
#define N1C 90000
#define N2C 60000
#define NTOT (N0C + N1C + N2C)   // 180000
#define DIN  256
#define DOUT 128
#define HEADS 4

#define TILEB  8192u             // 128 rows x 32 bf16 (64B) = 8KB
#define STAGEB (4u * TILEB)      // Ahi, Alo, Bhi, Blo
#define GSMEM  (2u * STAGEB + 1024u)

// ---------------- scratch (device globals; no runtime allocation) ------------
__device__ __align__(128) __nv_bfloat16 g_Xhi[(size_t)NTOT * DIN];
__device__ __align__(128) __nv_bfloat16 g_Xlo[(size_t)NTOT * DIN];
__device__ __align__(128) __nv_bfloat16 g_W1t_hi[HEADS * DOUT * DIN];    // [h][n][k]
__device__ __align__(128) __nv_bfloat16 g_W1t_lo[HEADS * DOUT * DIN];
__device__ __align__(128) __nv_bfloat16 g_Waggt_hi[HEADS * DOUT * 512];  // [h][n][k]
__device__ __align__(128) __nv_bfloat16 g_Waggt_lo[HEADS * DOUT * 512];
__device__ __align__(128) __nv_bfloat16 g_Yhi[(size_t)HEADS * NTOT * DOUT];
__device__ __align__(128) __nv_bfloat16 g_Ylo[(size_t)HEADS * NTOT * DOUT];
__device__ __align__(128) float g_a1 [HEADS * N0C];
__device__ __align__(128) float g_a2 [HEADS * NTOT];
__device__ __align__(128) float g_agg[(size_t)HEADS * 3 * N0C * DOUT];
__device__ __align__(128) __nv_bfloat16 g_agghi[(size_t)HEADS * 3 * N0C * DOUT];
__device__ __align__(128) __nv_bfloat16 g_agglo[(size_t)HEADS * 3 * N0C * DOUT];

// ---------------- PTX helpers (all base-ISA, no sm_100a features) -------------
__device__ __forceinline__ uint32_t smem_u32(const void* p) {
    uint32_t a;
    asm("{ .reg .u64 t; cvta.to.shared.u64 t, %1; cvt.u32.u64 %0, t; }" : "=r"(a) : "l"(p));
    return a;
}
__device__ __forceinline__ void cpa16(uint32_t dst, const void* src, uint32_t n) {
    asm volatile("cp.async.cg.shared.global [%0], [%1], 16, %2;" :: "r"(dst), "l"(src), "r"(n));
}
__device__ __forceinline__ void cp_commit() { asm volatile("cp.async.commit_group;" ::: "memory"); }
__device__ __forceinline__ void cpwait1()  { asm volatile("cp.async.wait_group 1;" ::: "memory"); }
__device__ __forceinline__ void cpwait0()  { asm volatile("cp.async.wait_group 0;" ::: "memory"); }

__device__ __forceinline__ void ldsm4(uint32_t* r, uint32_t addr) {
    asm volatile("ldmatrix.sync.aligned.m8n8.x4.shared.b16 {%0,%1,%2,%3}, [%4];"
                 : "=r"(r[0]), "=r"(r[1]), "=r"(r[2]), "=r"(r[3]) : "r"(addr));
}
__device__ __forceinline__ void mma16816(float* c, const uint32_t* a, const uint32_t* b) {
    asm volatile("mma.sync.aligned.m16n8k16.row.col.f32.bf16.bf16.f32 "
                 "{%0,%1,%2,%3}, {%4,%5,%6,%7}, {%8,%9}, {%0,%1,%2,%3};"
                 : "+f"(c[0]), "+f"(c[1]), "+f"(c[2]), "+f"(c[3])
                 : "r"(a[0]), "r"(a[1]), "r"(a[2]), "r"(a[3]), "r"(b[0]), "r"(b[1]));
}
// swizzled byte offset within a 128x32-bf16 tile: row r (0..127), 16B-chunk c (0..3)
__device__ __forceinline__ uint32_t swz(uint32_t r, uint32_t c) {
    return r * 64u + ((c ^ ((r >> 1) & 3u)) << 4);
}

// ---------------- split / pack helpers ----------------------------------------
__device__ __forceinline__ uint32_t pack2(__nv_bfloat16 a, __nv_bfloat16 b) {
    return (uint32_t)__bfloat16_as_ushort(a) | ((uint32_t)__bfloat16_as_ushort(b) << 16);
}
__device__ __forceinline__ void split1(float v, __nv_bfloat16& h, __nv_bfloat16& l) {
    h = __float2bfloat16(v);
    l = __float2bfloat16(v - __bfloat162float(h));
}

__global__ __launch_bounds__(256) void pack_x_kernel(
    const float* __restrict__ x0, const float* __restrict__ x1, const float* __restrict__ x2)
{
    size_t i = (size_t)blockIdx.x * 256 + threadIdx.x;   // float4 index
    if (i >= (size_t)NTOT * (DIN / 4)) return;
    int row = (int)(i >> 6);
    int c4  = (int)(i & 63);
    const float* src;
    if (row < N0C)            src = x0 + (size_t)row * DIN;
    else if (row < N0C + N1C) src = x1 + (size_t)(row - N0C) * DIN;
    else                      src = x2 + (size_t)(row - N0C - N1C) * DIN;
    float4 v = reinterpret_cast<const float4*>(src)[c4];
    __nv_bfloat16 h0,h1,h2,h3,l0,l1,l2,l3;
    split1(v.x,h0,l0); split1(v.y,h1,l1); split1(v.z,h2,l2); split1(v.w,h3,l3);
    reinterpret_cast<uint2*>(g_Xhi)[i] = make_uint2(pack2(h0,h1), pack2(h2,h3));
    reinterpret_cast<uint2*>(g_Xlo)[i] = make_uint2(pack2(l0,l1), pack2(l2,l3));
}

__global__ __launch_bounds__(256) void split_w1_kernel(const float* __restrict__ W1)
{
    int i = blockIdx.x * 256 + threadIdx.x;              // [h][n][k]
    if (i >= HEADS * DOUT * DIN) return;
    int h = i >> 15, n = (i >> 8) & 127, k = i & 255;
    float v = W1[(size_t)h * DIN * DOUT + (size_t)k * DOUT + n];
    __nv_bfloat16 hi, lo; split1(v, hi, lo);
    g_W1t_hi[i] = hi; g_W1t_lo[i] = lo;
}

__global__ __launch_bounds__(256) void split_wagg_kernel(const float* __restrict__ Wagg)
{
    int i = blockIdx.x * 256 + threadIdx.x;              // [h][n][k], k<512
    if (i >= HEADS * DOUT * 512) return;
    int h = i >> 16, n = (i >> 9) & 127, k = i & 511;
    float v = Wagg[(size_t)h * 512 * DOUT + (size_t)k * DOUT + n];
    __nv_bfloat16 hi, lo; split1(v, hi, lo);
    g_Waggt_hi[i] = hi; g_Waggt_lo[i] = lo;
}

__global__ __launch_bounds__(256) void split_agg_kernel()
{
    size_t i = (size_t)blockIdx.x * 256 + threadIdx.x;   // float4 index
    if (i >= (size_t)HEADS * 3 * N0C * DOUT / 4) return;
    float4 v = reinterpret_cast<const float4*>(g_agg)[i];
    __nv_bfloat16 h0,h1,h2,h3,l0,l1,l2,l3;
    split1(v.x,h0,l0); split1(v.y,h1,l1); split1(v.z,h2,l2); split1(v.w,h3,l3);
    reinterpret_cast<uint2*>(g_agghi)[i] = make_uint2(pack2(h0,h1), pack2(h2,h3));
    reinterpret_cast<uint2*>(g_agglo)[i] = make_uint2(pack2(l0,l1), pack2(l2,l3));
}

__global__ void zero_agg_kernel()
{
    const size_t n4 = (size_t)HEADS * 3 * N0C * DOUT / 4;
    size_t i = (size_t)blockIdx.x * blockDim.x + threadIdx.x;
    if (i < n4)
        reinterpret_cast<float4*>(g_agg)[i] = make_float4(0.f, 0.f, 0.f, 0.f);
}

// ---------------- shared MMA compute core --------------------------------------
// stage layout at s0: [Ahi 8K][Alo 8K][Bhi 8K][Blo 8K]; each tile 128x32 bf16.
// computes c += Ahi*Bhi + Ahi*Blo + Alo*Bhi over the 32-wide K chunk.
__device__ __forceinline__ void compute_stage(uint32_t s0, int mwarp, int nwarp,
                                              int lane, float c[2][8][4])
{
    uint32_t ah[2][2][4], al[2][2][4];
#pragma unroll
    for (int i = 0; i < 2; i++)
#pragma unroll
        for (int kk = 0; kk < 2; kk++) {
            uint32_t off = swz((uint32_t)(mwarp + i * 16 + (lane & 15)),
                               (uint32_t)(kk * 2 + (lane >> 4)));
            ldsm4(ah[i][kk], s0 + off);
            ldsm4(al[i][kk], s0 + TILEB + off);
        }
#pragma unroll
    for (int j = 0; j < 4; j++) {
        uint32_t nrow = (uint32_t)(nwarp + j * 16 + ((lane >> 4) << 3) + (lane & 7));
        uint32_t csel = (uint32_t)((lane >> 3) & 1);
#pragma unroll
        for (int kk = 0; kk < 2; kk++) {
            uint32_t off = swz(nrow, (uint32_t)(kk * 2) + csel);
            uint32_t bh[4], bl[4];
            ldsm4(bh, s0 + 2 * TILEB + off);
            ldsm4(bl, s0 + 3 * TILEB + off);
#pragma unroll
            for (int i = 0; i < 2; i++) {
                mma16816(c[i][j * 2 + 0], ah[i][kk], bh);
                mma16816(c[i][j * 2 + 1], ah[i][kk], bh + 2);
                mma16816(c[i][j * 2 + 0], ah[i][kk], bl);
                mma16816(c[i][j * 2 + 1], ah[i][kk], bl + 2);
                mma16816(c[i][j * 2 + 0], al[i][kk], bh);
                mma16816(c[i][j * 2 + 1], al[i][kk], bh + 2);
            }
        }
    }
}

// ---------------- GEMM1: Y = relu(X@W1[h]+b1[h]) -------------------------------
__global__ __launch_bounds__(256, 1) void gemm1_mma(const float* __restrict__ b1)
{
    extern __shared__ char smem[];
    __shared__ float sBias[128];
    uint32_t sb = smem_u32(smem);
    uint32_t tb = (sb + 1023u) & ~1023u;
    const int tid = threadIdx.x, lane = tid & 31, wid = tid >> 5;
    const int h = blockIdx.y, m0 = blockIdx.x * 128;
    const int mwarp = (wid & 3) * 32, nwarp = (wid >> 2) * 64;

    if (tid < 128) sBias[tid] = b1[h * DOUT + tid];

    float c[2][8][4];
#pragma unroll
    for (int i = 0; i < 2; i++)
#pragma unroll
        for (int j = 0; j < 8; j++)
#pragma unroll
            for (int q = 0; q < 4; q++) c[i][j][q] = 0.f;

    auto load = [&](int stage, int ks) {
        uint32_t s0 = tb + (uint32_t)stage * STAGEB;
        int k0 = ks * 32;
#pragma unroll
        for (int t = 0; t < 2; t++) {
            int idx = tid * 2 + t;           // 0..511
            int r = idx >> 2, cc = idx & 3;
            uint32_t dsw = swz((uint32_t)r, (uint32_t)cc);
            uint32_t n = (m0 + r < NTOT) ? 16u : 0u;
            size_t aoff = (size_t)(m0 + r) * DIN + k0 + cc * 8;
            size_t boff = ((size_t)h * DOUT + r) * DIN + k0 + cc * 8;
            cpa16(s0 + dsw,             g_Xhi    + aoff, n);
            cpa16(s0 + TILEB + dsw,     g_Xlo    + aoff, n);
            cpa16(s0 + 2 * TILEB + dsw, g_W1t_hi + boff, 16u);
            cpa16(s0 + 3 * TILEB + dsw, g_W1t_lo + boff, 16u);
        }
        cp_commit();
    };

    const int NKS = DIN / 32;   // 8
    load(0, 0);
    for (int ks = 0; ks < NKS; ks++) {
        if (ks + 1 < NKS) { load((ks + 1) & 1, ks + 1); cpwait1(); }
        else              { cpwait0(); }
        __syncthreads();
        compute_stage(tb + (uint32_t)(ks & 1) * STAGEB, mwarp, nwarp, lane, c);
        __syncthreads();
    }

    // epilogue: bias + relu, split to bf16 hi/lo, store
#pragma unroll
    for (int i = 0; i < 2; i++) {
        int r0 = m0 + mwarp + i * 16 + (lane >> 2);
#pragma unroll
        for (int v = 0; v < 2; v++) {
            int row = r0 + v * 8;
            if (row >= NTOT) continue;
            size_t yb = ((size_t)h * NTOT + row) * DOUT;
#pragma unroll
            for (int j = 0; j < 8; j++) {
                int col = nwarp + j * 8 + (lane & 3) * 2;
                float y0 = fmaxf(c[i][j][v * 2 + 0] + sBias[col], 0.f);
                float y1 = fmaxf(c[i][j][v * 2 + 1] + sBias[col + 1], 0.f);
                __nv_bfloat16 h0, l0, h1, l1;
                split1(y0, h0, l0); split1(y1, h1, l1);
                *reinterpret_cast<uint32_t*>(g_Yhi + yb + col) = pack2(h0, h1);
                *reinterpret_cast<uint32_t*>(g_Ylo + yb + col) = pack2(l0, l1);
            }
        }
    }
}

// ---------------- a1 / a2 GEMVs (bf16 hi/lo input) -----------------------------
__global__ __launch_bounds__(256) void a12_kernel(
    const float* __restrict__ a1w, const float* __restrict__ a1b,
    const float* __restrict__ a2w, const float* __restrict__ a2b)
{
    int w = blockIdx.x * 8 + (threadIdx.x >> 5);
    if (w >= HEADS * NTOT) return;
    int lane = threadIdx.x & 31;
    int h = w / NTOT;
    int r = w - h * NTOT;

    size_t yb = ((size_t)h * NTOT + r) * DOUT;
    uint2 uh = reinterpret_cast<const uint2*>(g_Yhi + yb)[lane];
    uint2 ul = reinterpret_cast<const uint2*>(g_Ylo + yb)[lane];
    float2 f0 = __bfloat1622float2(*reinterpret_cast<__nv_bfloat162*>(&uh.x));
    float2 f1 = __bfloat1622float2(*reinterpret_cast<__nv_bfloat162*>(&uh.y));
    float2 g0 = __bfloat1622float2(*reinterpret_cast<__nv_bfloat162*>(&ul.x));
    float2 g1 = __bfloat1622float2(*reinterpret_cast<__nv_bfloat162*>(&ul.y));
    float y0 = f0.x + g0.x, y1 = f0.y + g0.y, y2 = f1.x + g1.x, y3 = f1.y + g1.y;

    float4 w2 = reinterpret_cast<const float4*>(a2w + h * DOUT)[lane];
    float s2 = y0 * w2.x + y1 * w2.y + y2 * w2.z + y3 * w2.w;

    float s1 = 0.f;
    bool doA1 = (r < N0C);
    if (doA1) {
        float4 w1v = reinterpret_cast<const float4*>(a1w + h * DOUT)[lane];
        s1 = y0 * w1v.x + y1 * w1v.y + y2 * w1v.z + y3 * w1v.w;
    }
#pragma unroll
    for (int off = 16; off > 0; off >>= 1) {
        s2 += __shfl_xor_sync(0xffffffff, s2, off);
        s1 += __shfl_xor_sync(0xffffffff, s1, off);
    }
    if (lane == 0) {
        g_a2[h * NTOT + r] = s2 + a2b[h];
        if (doA1) g_a1[h * N0C + r] = s1 + a1b[h];
    }
}

// ---------------- attention scatter ---------------------------------------------
__global__ __launch_bounds__(256) void edge_kernel(
    const int* __restrict__ rows, const int* __restrict__ cols,
    int nnz, int colOffset, int level)
{
    int w = blockIdx.x * 8 + (threadIdx.x >> 5);
    if (w >= nnz) return;
    const int h = blockIdx.y;
    const int lane = threadIdx.x & 31;

    int r = __ldg(rows + w);
    int c = __ldg(cols + w);

    float av  = g_a1[h * N0C + r] + g_a2[h * NTOT + colOffset + c];
    float att = 1.f / (1.f + expf(-av));

    size_t yb = ((size_t)h * NTOT + colOffset + c) * DOUT;
    uint2 uh = reinterpret_cast<const uint2*>(g_Yhi + yb)[lane];
    uint2 ul = reinterpret_cast<const uint2*>(g_Ylo + yb)[lane];
    float2 f0 = __bfloat1622float2(*reinterpret_cast<__nv_bfloat162*>(&uh.x));
    float2 f1 = __bfloat1622float2(*reinterpret_cast<__nv_bfloat162*>(&uh.y));
    float2 g0 = __bfloat1622float2(*reinterpret_cast<__nv_bfloat162*>(&ul.x));
    float2 g1 = __bfloat1622float2(*reinterpret_cast<__nv_bfloat162*>(&ul.y));
    float4 v = make_float4((f0.x + g0.x) * att, (f0.y + g0.y) * att,
                           (f1.x + g1.x) * att, (f1.y + g1.y) * att);

    float* dst = g_agg + (((size_t)h * 3 + level) * N0C + r) * DOUT + lane * 4;
    asm volatile("red.global.add.v4.f32 [%0], {%1,%2,%3,%4};"
                 :: "l"(dst), "f"(v.x), "f"(v.y), "f"(v.z), "f"(v.w)
                 : "memory");
}

// ---------------- GEMM2: out = mean_h(cat_h @ Wagg[h]) + mean bias --------------
__global__ __launch_bounds__(256, 1) void gemm2_mma(
    const float* __restrict__ bagg, float* __restrict__ out)
{
    extern __shared__ char smem[];
    __shared__ float sBsum[128];
    uint32_t sb = smem_u32(smem);
    uint32_t tb = (sb + 1023u) & ~1023u;
    const int tid = threadIdx.x, lane = tid & 31, wid = tid >> 5;
    const int m0 = blockIdx.x * 128;
    const int mwarp = (wid & 3) * 32, nwarp = (wid >> 2) * 64;

    if (tid < 128)
        sBsum[tid] = bagg[tid] + bagg[128 + tid] + bagg[256 + tid] + bagg[384 + tid];

    float c[2][8][4];
#pragma unroll
    for (int i = 0; i < 2; i++)
#pragma unroll
        for (int j = 0; j < 8; j++)
#pragma unroll
            for (int q = 0; q < 4; q++) c[i][j][q] = 0.f;

    auto load = [&](int stage, int ks) {
        uint32_t s0 = tb + (uint32_t)stage * STAGEB;
        int chunk = ks >> 2, inner = ks & 3;
        int h = chunk >> 2, part = chunk & 3;
        const __nv_bfloat16 *ah, *al;
        size_t abase;
        if (part == 0) {
            abase = ((size_t)h * NTOT + m0) * DOUT;
            ah = g_Yhi; al = g_Ylo;
        } else {
            abase = ((size_t)(h * 3 + part - 1) * N0C + m0) * DOUT;
            ah = g_agghi; al = g_agglo;
        }
        size_t bbase = ((size_t)h * DOUT) * 512 + part * 128;
#pragma unroll
        for (int t = 0; t < 2; t++) {
            int idx = tid * 2 + t;
            int r = idx >> 2, cc = idx & 3;
            uint32_t dsw = swz((uint32_t)r, (uint32_t)cc);
            uint32_t n = (m0 + r < N0C) ? 16u : 0u;
            size_t aoff = abase + (size_t)r * DOUT + inner * 32 + cc * 8;
            size_t boff = bbase + (size_t)r * 512 + inner * 32 + cc * 8;
            cpa16(s0 + dsw,             ah + aoff, n);
            cpa16(s0 + TILEB + dsw,     al + aoff, n);
            cpa16(s0 + 2 * TILEB + dsw, g_Waggt_hi + boff, 16u);
            cpa16(s0 + 3 * TILEB + dsw, g_Waggt_lo + boff, 16u);
        }
        cp_commit();
    };

    const int NKS = 64;   // 4 heads * 4 parts * (128/32)
    load(0, 0);
    for (int ks = 0; ks < NKS; ks++) {
        if (ks + 1 < NKS) { load((ks + 1) & 1, ks + 1); cpwait1(); }
        else              { cpwait0(); }
        __syncthreads();
        compute_stage(tb + (uint32_t)(ks & 1) * STAGEB, mwarp, nwarp, lane, c);
        __syncthreads();
    }

    // epilogue: mean over heads + mean bias
#pragma unroll
    for (int i = 0; i < 2; i++) {
        int r0 = m0 + mwarp + i * 16 + (lane >> 2);
#pragma unroll
        for (int v = 0; v < 2; v++) {
            int row = r0 + v * 8;
            if (row >= N0C) continue;
            float* dst = out + (size_t)row * DOUT;
#pragma unroll
            for (int j = 0; j < 8; j++) {
                int col = nwarp + j * 8 + (lane & 3) * 2;
                float v0 = 0.25f * (c[i][j][v * 2 + 0] + sBsum[col]);
                float v1 = 0.25f * (c[i][j][v * 2 + 1] + sBsum[col + 1]);
                *reinterpret_cast<float2*>(dst + col) = make_float2(v0, v1);
            }
        }
    }
}

// ---------------- launcher -------------------------------------------------------
extern "C" void kernel_launch(void* const* d_in, const int* in_sizes, int n_in,
                              void* d_out, int out_size)
{
    const float* x0    = (const float*)d_in[0];
    const float* x1    = (const float*)d_in[1];
    const float* x2    = (const float*)d_in[2];
    const int*   rows0 = (const int*)  d_in[3];
    const int*   cols0 = (const int*)  d_in[4];
    const int*   rows1 = (const int*)  d_in[5];
    const int*   cols1 = (const int*)  d_in[6];
    const int*   rows2 = (const int*)  d_in[7];
    const int*   cols2 = (const int*)  d_in[8];
    const float* W1    = (const float*)d_in[9];
    const float* b1    = (const float*)d_in[10];
    const float* a1w   = (const float*)d_in[11];
    const float* a1b   = (const float*)d_in[12];
    const float* a2w   = (const float*)d_in[13];
    const float* a2b   = (const float*)d_in[14];
    const float* Wagg  = (const float*)d_in[15];
    const float* bagg  = (const float*)d_in[16];
    float* out = (float*)d_out;

    const int nnz0 = in_sizes[3];
    const int nnz1 = in_sizes[5];
    const int nnz2 = in_sizes[7];

    static bool attr_done = false;
    if (!attr_done) {
        cudaFuncSetAttribute(gemm1_mma, cudaFuncAttributeMaxDynamicSharedMemorySize, GSMEM);
        cudaFuncSetAttribute(gemm2_mma, cudaFuncAttributeMaxDynamicSharedMemorySize, GSMEM);
        attr_done = true;
    }

    // 0) split inputs into bf16 hi/lo
    pack_x_kernel<<<(NTOT * (DIN / 4) + 255) / 256, 256>>>(x0, x1, x2);
    split_w1_kernel<<<(HEADS * DOUT * DIN + 255) / 256, 256>>>(W1);
    split_wagg_kernel<<<(HEADS * DOUT * 512 + 255) / 256, 256>>>(Wagg);
    zero_agg_kernel<<<(11520000 + 255) / 256, 256>>>();

    // 1) linear + relu for all levels (tensor cores)
    gemm1_mma<<<dim3((NTOT + 127) / 128, HEADS), 256, GSMEM>>>(b1);

    // 2) attention scalar terms
    a12_kernel<<<(HEADS * NTOT + 7) / 8, 256>>>(a1w, a1b, a2w, a2b);

    // 3) attention-weighted scatter
    edge_kernel<<<dim3((nnz0 + 7) / 8, HEADS), 256>>>(rows0, cols0, nnz0, 0, 0);
    edge_kernel<<<dim3((nnz1 + 7) / 8, HEADS), 256>>>(rows1, cols1, nnz1, N0C, 1);
    edge_kernel<<<dim3((nnz2 + 7) / 8, HEADS), 256>>>(rows2, cols2, nnz2, N0C + N1C, 2);

    // 4) split agg for the output GEMM
    split_agg_kernel<<<(11520000 + 255) / 256, 256>>>();

    // 5) concat + output projection + head mean (tensor cores)
    gemm2_mma<<<(N0C + 127) / 128, 256, GSMEM>>>(bagg, out);
}

// round 5
// speedup vs baseline: 2.0772x; 1.4944x over previous
#include <cuda_runtime.h>
#include <cuda_bf16.h>
#include <math.h>
#include <stdint.h>

#define N0C 30000
#define N1C 90000
#define N2C 60000
#define NTOT (N0C + N1C + N2C)   // 180000
#define DIN  256
#define DOUT 128
#define HEADS 4
#define EMAX 1320000             // max total edges across 3 levels

#define TILEB  8192u             // 128 rows x 32 bf16 (64B) = 8KB
#define STAGEB (4u * TILEB)      // Ahi, Alo, Bhi, Blo
#define GSMEM  (2u * STAGEB + 1024u)

// ---------------- scratch (device globals; no runtime allocation) ------------
__device__ __align__(128) __nv_bfloat16 g_Xhi[(size_t)NTOT * DIN];
__device__ __align__(128) __nv_bfloat16 g_Xlo[(size_t)NTOT * DIN];
__device__ __align__(128) __nv_bfloat16 g_W1t_hi[HEADS * DOUT * DIN];    // [h][n][k]
__device__ __align__(128) __nv_bfloat16 g_W1t_lo[HEADS * DOUT * DIN];
__device__ __align__(128) __nv_bfloat16 g_Waggt_hi[HEADS * DOUT * 512];  // [h][n][k]
__device__ __align__(128) __nv_bfloat16 g_Waggt_lo[HEADS * DOUT * 512];
__device__ __align__(128) __nv_bfloat16 g_Yhi[(size_t)HEADS * NTOT * DOUT];
__device__ __align__(128) __nv_bfloat16 g_Ylo[(size_t)HEADS * NTOT * DOUT]; // only rows<N0C written
__device__ __align__(128) float g_a1 [HEADS * N0C];
__device__ __align__(128) float g_a2 [HEADS * NTOT];
__device__ __align__(128) __nv_bfloat16 g_agghi[(size_t)HEADS * 3 * N0C * DOUT];
__device__ __align__(128) __nv_bfloat16 g_agglo[(size_t)HEADS * 3 * N0C * DOUT];
// CSR scratch
__device__ int g_cnt   [3 * N0C];
__device__ int g_rowptr[3 * (N0C + 1)];
__device__ int g_pos   [3 * N0C];
__device__ int g_ecol  [EMAX];

// ---------------- PTX helpers (all base-ISA) ----------------------------------
__device__ __forceinline__ uint32_t smem_u32(const void* p) {
    uint32_t a;
    asm("{ .reg .u64 t; cvta.to.shared.u64 t, %1; cvt.u32.u64 %0, t; }" : "=r"(a) : "l"(p));
    return a;
}
__device__ __forceinline__ void cpa16(uint32_t dst, const void* src, uint32_t n) {
    asm volatile("cp.async.cg.shared.global [%0], [%1], 16, %2;" :: "r"(dst), "l"(src), "r"(n));
}
__device__ __forceinline__ void cp_commit() { asm volatile("cp.async.commit_group;" ::: "memory"); }
__device__ __forceinline__ void cpwait1()  { asm volatile("cp.async.wait_group 1;" ::: "memory"); }
__device__ __forceinline__ void cpwait0()  { asm volatile("cp.async.wait_group 0;" ::: "memory"); }

__device__ __forceinline__ void ldsm4(uint32_t* r, uint32_t addr) {
    asm volatile("ldmatrix.sync.aligned.m8n8.x4.shared.b16 {%0,%1,%2,%3}, [%4];"
                 : "=r"(r[0]), "=r"(r[1]), "=r"(r[2]), "=r"(r[3]) : "r"(addr));
}
__device__ __forceinline__ void mma16816(float* c, const uint32_t* a, const uint32_t* b) {
    asm volatile("mma.sync.aligned.m16n8k16.row.col.f32.bf16.bf16.f32 "
                 "{%0,%1,%2,%3}, {%4,%5,%6,%7}, {%8,%9}, {%0,%1,%2,%3};"
                 : "+f"(c[0]), "+f"(c[1]), "+f"(c[2]), "+f"(c[3])
                 : "r"(a[0]), "r"(a[1]), "r"(a[2]), "r"(a[3]), "r"(b[0]), "r"(b[1]));
}
__device__ __forceinline__ uint32_t swz(uint32_t r, uint32_t c) {
    return r * 64u + ((c ^ ((r >> 1) & 3u)) << 4);
}

// ---------------- split / pack helpers ----------------------------------------
__device__ __forceinline__ uint32_t pack2(__nv_bfloat16 a, __nv_bfloat16 b) {
    return (uint32_t)__bfloat16_as_ushort(a) | ((uint32_t)__bfloat16_as_ushort(b) << 16);
}
__device__ __forceinline__ void split1(float v, __nv_bfloat16& h, __nv_bfloat16& l) {
    h = __float2bfloat16(v);
    l = __float2bfloat16(v - __bfloat162float(h));
}

__global__ __launch_bounds__(256) void pack_x_kernel(
    const float* __restrict__ x0, const float* __restrict__ x1, const float* __restrict__ x2)
{
    size_t i = (size_t)blockIdx.x * 256 + threadIdx.x;   // float4 index
    if (i >= (size_t)NTOT * (DIN / 4)) return;
    int row = (int)(i >> 6);
    int c4  = (int)(i & 63);
    const float* src;
    if (row < N0C)            src = x0 + (size_t)row * DIN;
    else if (row < N0C + N1C) src = x1 + (size_t)(row - N0C) * DIN;
    else                      src = x2 + (size_t)(row - N0C - N1C) * DIN;
    float4 v = reinterpret_cast<const float4*>(src)[c4];
    __nv_bfloat16 h0,h1,h2,h3,l0,l1,l2,l3;
    split1(v.x,h0,l0); split1(v.y,h1,l1); split1(v.z,h2,l2); split1(v.w,h3,l3);
    reinterpret_cast<uint2*>(g_Xhi)[i] = make_uint2(pack2(h0,h1), pack2(h2,h3));
    reinterpret_cast<uint2*>(g_Xlo)[i] = make_uint2(pack2(l0,l1), pack2(l2,l3));
}

__global__ __launch_bounds__(256) void split_w1_kernel(const float* __restrict__ W1)
{
    int i = blockIdx.x * 256 + threadIdx.x;              // [h][n][k]
    if (i >= HEADS * DOUT * DIN) return;
    int h = i >> 15, n = (i >> 8) & 127, k = i & 255;
    float v = W1[(size_t)h * DIN * DOUT + (size_t)k * DOUT + n];
    __nv_bfloat16 hi, lo; split1(v, hi, lo);
    g_W1t_hi[i] = hi; g_W1t_lo[i] = lo;
}

__global__ __launch_bounds__(256) void split_wagg_kernel(const float* __restrict__ Wagg)
{
    int i = blockIdx.x * 256 + threadIdx.x;              // [h][n][k], k<512
    if (i >= HEADS * DOUT * 512) return;
    int h = i >> 16, n = (i >> 9) & 127, k = i & 511;
    float v = Wagg[(size_t)h * 512 * DOUT + (size_t)k * DOUT + n];
    __nv_bfloat16 hi, lo; split1(v, hi, lo);
    g_Waggt_hi[i] = hi; g_Waggt_lo[i] = lo;
}

// zero a1, a2, cnt in one sweep
__global__ __launch_bounds__(256) void zero_small_kernel()
{
    int i = blockIdx.x * 256 + threadIdx.x;
    if (i < HEADS * N0C)  g_a1[i] = 0.f;
    if (i < HEADS * NTOT) g_a2[i] = 0.f;
    if (i < 3 * N0C)      g_cnt[i] = 0;
}

// ---------------- CSR build ----------------------------------------------------
__global__ __launch_bounds__(256) void hist_kernel(const int* __restrict__ rows, int nnz, int lvl)
{
    int i = blockIdx.x * 256 + threadIdx.x;
    if (i < nnz) atomicAdd(&g_cnt[lvl * N0C + rows[i]], 1);
}

__global__ __launch_bounds__(1024) void scan_kernel()   // grid = 3 (one block per level)
{
    const int lvl = blockIdx.x;
    const int* cnt = g_cnt + lvl * N0C;
    int* rp  = g_rowptr + lvl * (N0C + 1);
    int* pos = g_pos + lvl * N0C;
    __shared__ int ssum[1024];
    const int CH = (N0C + 1023) / 1024;   // 30
    int t = threadIdx.x;
    int base = t * CH;
    int s = 0;
    for (int k = 0; k < CH; k++) { int idx = base + k; if (idx < N0C) s += cnt[idx]; }
    ssum[t] = s; __syncthreads();
    for (int off = 1; off < 1024; off <<= 1) {
        int v = (t >= off) ? ssum[t - off] : 0;
        __syncthreads();
        ssum[t] += v;
        __syncthreads();
    }
    int run = (t == 0) ? 0 : ssum[t - 1];
    for (int k = 0; k < CH; k++) {
        int idx = base + k;
        if (idx < N0C) { rp[idx] = run; pos[idx] = run; run += cnt[idx]; }
    }
    if (t == 1023) rp[N0C] = run;
}

__global__ __launch_bounds__(256) void scatter_kernel(
    const int* __restrict__ rows, const int* __restrict__ cols,
    int nnz, int lvl, int ebase)
{
    int i = blockIdx.x * 256 + threadIdx.x;
    if (i >= nnz) return;
    int p = atomicAdd(&g_pos[lvl * N0C + rows[i]], 1);
    g_ecol[ebase + p] = cols[i];
}

// ---------------- shared MMA compute core --------------------------------------
__device__ __forceinline__ void compute_stage(uint32_t s0, int mwarp, int nwarp,
                                              int lane, float c[2][8][4])
{
    uint32_t ah[2][2][4], al[2][2][4];
#pragma unroll
    for (int i = 0; i < 2; i++)
#pragma unroll
        for (int kk = 0; kk < 2; kk++) {
            uint32_t off = swz((uint32_t)(mwarp + i * 16 + (lane & 15)),
                               (uint32_t)(kk * 2 + (lane >> 4)));
            ldsm4(ah[i][kk], s0 + off);
            ldsm4(al[i][kk], s0 + TILEB + off);
        }
#pragma unroll
    for (int j = 0; j < 4; j++) {
        uint32_t nrow = (uint32_t)(nwarp + j * 16 + ((lane >> 4) << 3) + (lane & 7));
        uint32_t csel = (uint32_t)((lane >> 3) & 1);
#pragma unroll
        for (int kk = 0; kk < 2; kk++) {
            uint32_t off = swz(nrow, (uint32_t)(kk * 2) + csel);
            uint32_t bh[4], bl[4];
            ldsm4(bh, s0 + 2 * TILEB + off);
            ldsm4(bl, s0 + 3 * TILEB + off);
#pragma unroll
            for (int i = 0; i < 2; i++) {
                mma16816(c[i][j * 2 + 0], ah[i][kk], bh);
                mma16816(c[i][j * 2 + 1], ah[i][kk], bh + 2);
                mma16816(c[i][j * 2 + 0], ah[i][kk], bl);
                mma16816(c[i][j * 2 + 1], ah[i][kk], bl + 2);
                mma16816(c[i][j * 2 + 0], al[i][kk], bh);
                mma16816(c[i][j * 2 + 1], al[i][kk], bh + 2);
            }
        }
    }
}

// ---------------- GEMM1: Y = relu(X@W1[h]+b1[h]) + fused a1/a2 partial dots ----
__global__ __launch_bounds__(256, 1) void gemm1_mma(
    const float* __restrict__ b1, const float* __restrict__ a1w,
    const float* __restrict__ a2w)
{
    extern __shared__ char smem[];
    __shared__ float sBias[128], sA1w[128], sA2w[128];
    uint32_t sb = smem_u32(smem);
    uint32_t tb = (sb + 1023u) & ~1023u;
    const int tid = threadIdx.x, lane = tid & 31, wid = tid >> 5;
    const int h = blockIdx.y, m0 = blockIdx.x * 128;
    const int mwarp = (wid & 3) * 32, nwarp = (wid >> 2) * 64;

    if (tid < 128) {
        sBias[tid] = b1[h * DOUT + tid];
        sA1w[tid]  = a1w[h * DOUT + tid];
        sA2w[tid]  = a2w[h * DOUT + tid];
    }

    float c[2][8][4];
#pragma unroll
    for (int i = 0; i < 2; i++)
#pragma unroll
        for (int j = 0; j < 8; j++)
#pragma unroll
            for (int q = 0; q < 4; q++) c[i][j][q] = 0.f;

    auto load = [&](int stage, int ks) {
        uint32_t s0 = tb + (uint32_t)stage * STAGEB;
        int k0 = ks * 32;
#pragma unroll
        for (int t = 0; t < 2; t++) {
            int idx = tid * 2 + t;
            int r = idx >> 2, cc = idx & 3;
            uint32_t dsw = swz((uint32_t)r, (uint32_t)cc);
            uint32_t n = (m0 + r < NTOT) ? 16u : 0u;
            size_t aoff = (size_t)(m0 + r) * DIN + k0 + cc * 8;
            size_t boff = ((size_t)h * DOUT + r) * DIN + k0 + cc * 8;
            cpa16(s0 + dsw,             g_Xhi    + aoff, n);
            cpa16(s0 + TILEB + dsw,     g_Xlo    + aoff, n);
            cpa16(s0 + 2 * TILEB + dsw, g_W1t_hi + boff, 16u);
            cpa16(s0 + 3 * TILEB + dsw, g_W1t_lo + boff, 16u);
        }
        cp_commit();
    };

    const int NKS = DIN / 32;   // 8
    load(0, 0);
    for (int ks = 0; ks < NKS; ks++) {
        if (ks + 1 < NKS) { load((ks + 1) & 1, ks + 1); cpwait1(); }
        else              { cpwait0(); }
        __syncthreads();
        compute_stage(tb + (uint32_t)(ks & 1) * STAGEB, mwarp, nwarp, lane, c);
        __syncthreads();
    }

    // epilogue: bias + relu, split to bf16 hi/lo, fused a1/a2 partial dots
#pragma unroll
    for (int i = 0; i < 2; i++) {
        int r0 = m0 + mwarp + i * 16 + (lane >> 2);
#pragma unroll
        for (int v = 0; v < 2; v++) {
            int row = r0 + v * 8;
            if (row >= NTOT) continue;
            size_t yb = ((size_t)h * NTOT + row) * DOUT;
            bool lo_keep = (row < N0C);
            float p1 = 0.f, p2 = 0.f;
#pragma unroll
            for (int j = 0; j < 8; j++) {
                int col = nwarp + j * 8 + (lane & 3) * 2;
                float y0 = fmaxf(c[i][j][v * 2 + 0] + sBias[col], 0.f);
                float y1 = fmaxf(c[i][j][v * 2 + 1] + sBias[col + 1], 0.f);
                p1 = fmaf(y0, sA1w[col], p1); p1 = fmaf(y1, sA1w[col + 1], p1);
                p2 = fmaf(y0, sA2w[col], p2); p2 = fmaf(y1, sA2w[col + 1], p2);
                __nv_bfloat16 h0, l0, h1, l1;
                split1(y0, h0, l0); split1(y1, h1, l1);
                *reinterpret_cast<uint32_t*>(g_Yhi + yb + col) = pack2(h0, h1);
                if (lo_keep)
                    *reinterpret_cast<uint32_t*>(g_Ylo + yb + col) = pack2(l0, l1);
            }
            atomicAdd(&g_a2[h * NTOT + row], p2);
            if (lo_keep) atomicAdd(&g_a1[h * N0C + row], p1);
        }
    }
}

// ---------------- edge aggregation (CSR, register accumulate) ------------------
// one warp per (row, level); gridDim.y = head
__global__ __launch_bounds__(256) void edge_agg_kernel(
    const float* __restrict__ a1b, const float* __restrict__ a2b,
    int ebase1, int ebase2)
{
    int w = blockIdx.x * 8 + (threadIdx.x >> 5);
    if (w >= N0C * 3) return;
    const int h = blockIdx.y;
    const int lane = threadIdx.x & 31;
    int row = w / 3;
    int lvl = w - row * 3;

    int coff, eb;
    if (lvl == 0)      { coff = 0;          eb = 0; }
    else if (lvl == 1) { coff = N0C;        eb = ebase1; }
    else               { coff = N0C + N1C;  eb = ebase2; }

    int beg = g_rowptr[lvl * (N0C + 1) + row];
    int end = g_rowptr[lvl * (N0C + 1) + row + 1];

    const float a1r  = g_a1[h * N0C + row] + a1b[h] + a2b[h];
    const float* a2h = g_a2 + h * NTOT + coff;
    const __nv_bfloat16* yh = g_Yhi + ((size_t)h * NTOT + coff) * DOUT;
    const int* ec = g_ecol + eb;

    float ax = 0.f, ay = 0.f, az = 0.f, aw = 0.f;
    int e = beg;
    for (; e + 1 < end; e += 2) {
        int c0 = __ldg(ec + e);
        int c1 = __ldg(ec + e + 1);
        float t0 = a1r + __ldg(a2h + c0);
        float t1 = a1r + __ldg(a2h + c1);
        uint2 u0 = *reinterpret_cast<const uint2*>(yh + (size_t)c0 * DOUT + lane * 4);
        uint2 u1 = *reinterpret_cast<const uint2*>(yh + (size_t)c1 * DOUT + lane * 4);
        float att0 = __fdividef(1.f, 1.f + __expf(-t0));
        float att1 = __fdividef(1.f, 1.f + __expf(-t1));
        float2 f0 = __bfloat1622float2(*reinterpret_cast<__nv_bfloat162*>(&u0.x));
        float2 f1 = __bfloat1622float2(*reinterpret_cast<__nv_bfloat162*>(&u0.y));
        float2 g0 = __bfloat1622float2(*reinterpret_cast<__nv_bfloat162*>(&u1.x));
        float2 g1 = __bfloat1622float2(*reinterpret_cast<__nv_bfloat162*>(&u1.y));
        ax = fmaf(att0, f0.x, ax); ay = fmaf(att0, f0.y, ay);
        az = fmaf(att0, f1.x, az); aw = fmaf(att0, f1.y, aw);
        ax = fmaf(att1, g0.x, ax); ay = fmaf(att1, g0.y, ay);
        az = fmaf(att1, g1.x, az); aw = fmaf(att1, g1.y, aw);
    }
    if (e < end) {
        int c0 = __ldg(ec + e);
        float t0 = a1r + __ldg(a2h + c0);
        uint2 u0 = *reinterpret_cast<const uint2*>(yh + (size_t)c0 * DOUT + lane * 4);
        float att0 = __fdividef(1.f, 1.f + __expf(-t0));
        float2 f0 = __bfloat1622float2(*reinterpret_cast<__nv_bfloat162*>(&u0.x));
        float2 f1 = __bfloat1622float2(*reinterpret_cast<__nv_bfloat162*>(&u0.y));
        ax = fmaf(att0, f0.x, ax); ay = fmaf(att0, f0.y, ay);
        az = fmaf(att0, f1.x, az); aw = fmaf(att0, f1.y, aw);
    }

    // split to bf16 hi/lo and store (no atomics needed)
    __nv_bfloat16 h0,h1,h2,h3,l0,l1,l2,l3;
    split1(ax,h0,l0); split1(ay,h1,l1); split1(az,h2,l2); split1(aw,h3,l3);
    size_t ob = (((size_t)h * 3 + lvl) * N0C + row) * DOUT + lane * 4;
    *reinterpret_cast<uint2*>(g_agghi + ob) = make_uint2(pack2(h0,h1), pack2(h2,h3));
    *reinterpret_cast<uint2*>(g_agglo + ob) = make_uint2(pack2(l0,l1), pack2(l2,l3));
}

// ---------------- GEMM2: out = mean_h(cat_h @ Wagg[h]) + mean bias --------------
__global__ __launch_bounds__(256, 1) void gemm2_mma(
    const float* __restrict__ bagg, float* __restrict__ out)
{
    extern __shared__ char smem[];
    __shared__ float sBsum[128];
    uint32_t sb = smem_u32(smem);
    uint32_t tb = (sb + 1023u) & ~1023u;
    const int tid = threadIdx.x, lane = tid & 31, wid = tid >> 5;
    const int m0 = blockIdx.x * 128;
    const int mwarp = (wid & 3) * 32, nwarp = (wid >> 2) * 64;

    if (tid < 128)
        sBsum[tid] = bagg[tid] + bagg[128 + tid] + bagg[256 + tid] + bagg[384 + tid];

    float c[2][8][4];
#pragma unroll
    for (int i = 0; i < 2; i++)
#pragma unroll
        for (int j = 0; j < 8; j++)
#pragma unroll
            for (int q = 0; q < 4; q++) c[i][j][q] = 0.f;

    auto load = [&](int stage, int ks) {
        uint32_t s0 = tb + (uint32_t)stage * STAGEB;
        int chunk = ks >> 2, inner = ks & 3;
        int h = chunk >> 2, part = chunk & 3;
        const __nv_bfloat16 *ah, *al;
        size_t abase;
        if (part == 0) {
            abase = ((size_t)h * NTOT + m0) * DOUT;
            ah = g_Yhi; al = g_Ylo;
        } else {
            abase = ((size_t)(h * 3 + part - 1) * N0C + m0) * DOUT;
            ah = g_agghi; al = g_agglo;
        }
        size_t bbase = ((size_t)h * DOUT) * 512 + part * 128;
#pragma unroll
        for (int t = 0; t < 2; t++) {
            int idx = tid * 2 + t;
            int r = idx >> 2, cc = idx & 3;
            uint32_t dsw = swz((uint32_t)r, (uint32_t)cc);
            uint32_t n = (m0 + r < N0C) ? 16u : 0u;
            size_t aoff = abase + (size_t)r * DOUT + inner * 32 + cc * 8;
            size_t boff = bbase + (size_t)r * 512 + inner * 32 + cc * 8;
            cpa16(s0 + dsw,             ah + aoff, n);
            cpa16(s0 + TILEB + dsw,     al + aoff, n);
            cpa16(s0 + 2 * TILEB + dsw, g_Waggt_hi + boff, 16u);
            cpa16(s0 + 3 * TILEB + dsw, g_Waggt_lo + boff, 16u);
        }
        cp_commit();
    };

    const int NKS = 64;
    load(0, 0);
    for (int ks = 0; ks < NKS; ks++) {
        if (ks + 1 < NKS) { load((ks + 1) & 1, ks + 1); cpwait1(); }
        else              { cpwait0(); }
        __syncthreads();
        compute_stage(tb + (uint32_t)(ks & 1) * STAGEB, mwarp, nwarp, lane, c);
        __syncthreads();
    }

#pragma unroll
    for (int i = 0; i < 2; i++) {
        int r0 = m0 + mwarp + i * 16 + (lane >> 2);
#pragma unroll
        for (int v = 0; v < 2; v++) {
            int row = r0 + v * 8;
            if (row >= N0C) continue;
            float* dst = out + (size_t)row * DOUT;
#pragma unroll
            for (int j = 0; j < 8; j++) {
                int col = nwarp + j * 8 + (lane & 3) * 2;
                float v0 = 0.25f * (c[i][j][v * 2 + 0] + sBsum[col]);
                float v1 = 0.25f * (c[i][j][v * 2 + 1] + sBsum[col + 1]);
                *reinterpret_cast<float2*>(dst + col) = make_float2(v0, v1);
            }
        }
    }
}

// ---------------- launcher -------------------------------------------------------
extern "C" void kernel_launch(void* const* d_in, const int* in_sizes, int n_in,
                              void* d_out, int out_size)
{
    const float* x0    = (const float*)d_in[0];
    const float* x1    = (const float*)d_in[1];
    const float* x2    = (const float*)d_in[2];
    const int*   rows0 = (const int*)  d_in[3];
    const int*   cols0 = (const int*)  d_in[4];
    const int*   rows1 = (const int*)  d_in[5];
    const int*   cols1 = (const int*)  d_in[6];
    const int*   rows2 = (const int*)  d_in[7];
    const int*   cols2 = (const int*)  d_in[8];
    const float* W1    = (const float*)d_in[9];
    const float* b1    = (const float*)d_in[10];
    const float* a1w   = (const float*)d_in[11];
    const float* a1b   = (const float*)d_in[12];
    const float* a2w   = (const float*)d_in[13];
    const float* a2b   = (const float*)d_in[14];
    const float* Wagg  = (const float*)d_in[15];
    const float* bagg  = (const float*)d_in[16];
    float* out = (float*)d_out;

    const int nnz0 = in_sizes[3];
    const int nnz1 = in_sizes[5];
    const int nnz2 = in_sizes[7];

    static bool attr_done = false;
    if (!attr_done) {
        cudaFuncSetAttribute(gemm1_mma, cudaFuncAttributeMaxDynamicSharedMemorySize, GSMEM);
        cudaFuncSetAttribute(gemm2_mma, cudaFuncAttributeMaxDynamicSharedMemorySize, GSMEM);
        attr_done = true;
    }

    // 0) split inputs into bf16 hi/lo, zero small scratch
    pack_x_kernel<<<(NTOT * (DIN / 4) + 255) / 256, 256>>>(x0, x1, x2);
    split_w1_kernel<<<(HEADS * DOUT * DIN + 255) / 256, 256>>>(W1);
    split_wagg_kernel<<<(HEADS * DOUT * 512 + 255) / 256, 256>>>(Wagg);
    zero_small_kernel<<<(HEADS * NTOT + 255) / 256, 256>>>();

    // 1) CSR build (shared across heads)
    hist_kernel<<<(nnz0 + 255) / 256, 256>>>(rows0, nnz0, 0);
    hist_kernel<<<(nnz1 + 255) / 256, 256>>>(rows1, nnz1, 1);
    hist_kernel<<<(nnz2 + 255) / 256, 256>>>(rows2, nnz2, 2);
    scan_kernel<<<3, 1024>>>();
    scatter_kernel<<<(nnz0 + 255) / 256, 256>>>(rows0, cols0, nnz0, 0, 0);
    scatter_kernel<<<(nnz1 + 255) / 256, 256>>>(rows1, cols1, nnz1, 1, nnz0);
    scatter_kernel<<<(nnz2 + 255) / 256, 256>>>(rows2, cols2, nnz2, 2, nnz0 + nnz1);

    // 2) linear + relu for all levels (tensor cores), fused a1/a2 dots
    gemm1_mma<<<dim3((NTOT + 127) / 128, HEADS), 256, GSMEM>>>(b1, a1w, a2w);

    // 3) attention-weighted aggregation (CSR, no atomics)
    edge_agg_kernel<<<dim3((N0C * 3 + 7) / 8, HEADS), 256>>>(a1b, a2b, nnz0, nnz0 + nnz1);

    // 4) concat + output projection + head mean (tensor cores)
    gemm2_mma<<<(N0C + 127) / 128, 256, GSMEM>>>(bagg, out);
}

// round 6
// speedup vs baseline: 2.1304x; 1.0256x over previous
#include <cuda_runtime.h>
#include <cuda_bf16.h>
#include <cuda_fp16.h>
#include <math.h>
#include <stdint.h>

#define N0C 30000
#define N1C 90000
#define N2C 60000
#define NTOT (N0C + N1C + N2C)   // 180000
#define DIN  256
#define DOUT 128
#define HEADS 4
#define EMAX 1320000

#define TILEB  8192u             // 128 rows x 32 bf16 (64B) = 8KB
#define STAGEB (4u * TILEB)      // Ahi, Alo, Bhi, Blo
#define GSMEM  (2u * STAGEB + 1024u)

// ---------------- scratch (device globals; no runtime allocation) ------------
__device__ __align__(128) __nv_bfloat16 g_Xhi[(size_t)NTOT * DIN];
__device__ __align__(128) __nv_bfloat16 g_Xlo[(size_t)NTOT * DIN];
__device__ __align__(128) __nv_bfloat16 g_W1t_hi[HEADS * DOUT * DIN];    // [h][n][k]
__device__ __align__(128) __nv_bfloat16 g_W1t_lo[HEADS * DOUT * DIN];
__device__ __align__(128) __nv_bfloat16 g_Waggt_hi[HEADS * DOUT * 512];  // [h][n][k]
__device__ __align__(128) __nv_bfloat16 g_Waggt_lo[HEADS * DOUT * 512];
__device__ __align__(128) __half        g_Yf16[(size_t)HEADS * NTOT * DOUT]; // all rows (edge gather)
__device__ __align__(128) __nv_bfloat16 g_Yhi[(size_t)HEADS * N0C * DOUT];   // rows<N0C (gemm2 A)
__device__ __align__(128) __nv_bfloat16 g_Ylo[(size_t)HEADS * N0C * DOUT];
__device__ __align__(128) float g_a1 [HEADS * N0C];
__device__ __align__(128) float g_a2 [HEADS * NTOT];
__device__ __align__(128) __nv_bfloat16 g_agghi[(size_t)HEADS * 3 * N0C * DOUT];
__device__ __align__(128) __nv_bfloat16 g_agglo[(size_t)HEADS * 3 * N0C * DOUT];
// CSR scratch
__device__ int g_cnt   [3 * N0C];
__device__ int g_rowptr[3 * (N0C + 1)];
__device__ int g_pos   [3 * N0C];
__device__ int g_ecol  [EMAX];

// ---------------- PTX helpers (all base-ISA) ----------------------------------
__device__ __forceinline__ uint32_t smem_u32(const void* p) {
    uint32_t a;
    asm("{ .reg .u64 t; cvta.to.shared.u64 t, %1; cvt.u32.u64 %0, t; }" : "=r"(a) : "l"(p));
    return a;
}
__device__ __forceinline__ void cpa16(uint32_t dst, const void* src, uint32_t n) {
    asm volatile("cp.async.cg.shared.global [%0], [%1], 16, %2;" :: "r"(dst), "l"(src), "r"(n));
}
__device__ __forceinline__ void cp_commit() { asm volatile("cp.async.commit_group;" ::: "memory"); }
__device__ __forceinline__ void cpwait1()  { asm volatile("cp.async.wait_group 1;" ::: "memory"); }
__device__ __forceinline__ void cpwait0()  { asm volatile("cp.async.wait_group 0;" ::: "memory"); }

__device__ __forceinline__ void ldsm4(uint32_t* r, uint32_t addr) {
    asm volatile("ldmatrix.sync.aligned.m8n8.x4.shared.b16 {%0,%1,%2,%3}, [%4];"
                 : "=r"(r[0]), "=r"(r[1]), "=r"(r[2]), "=r"(r[3]) : "r"(addr));
}
__device__ __forceinline__ void mma16816(float* c, const uint32_t* a, const uint32_t* b) {
    asm volatile("mma.sync.aligned.m16n8k16.row.col.f32.bf16.bf16.f32 "
                 "{%0,%1,%2,%3}, {%4,%5,%6,%7}, {%8,%9}, {%0,%1,%2,%3};"
                 : "+f"(c[0]), "+f"(c[1]), "+f"(c[2]), "+f"(c[3])
                 : "r"(a[0]), "r"(a[1]), "r"(a[2]), "r"(a[3]), "r"(b[0]), "r"(b[1]));
}
__device__ __forceinline__ uint32_t swz(uint32_t r, uint32_t c) {
    return r * 64u + ((c ^ ((r >> 1) & 3u)) << 4);
}

// ---------------- split / pack helpers ----------------------------------------
__device__ __forceinline__ uint32_t pack2(__nv_bfloat16 a, __nv_bfloat16 b) {
    return (uint32_t)__bfloat16_as_ushort(a) | ((uint32_t)__bfloat16_as_ushort(b) << 16);
}
__device__ __forceinline__ uint32_t pack2h(__half a, __half b) {
    return (uint32_t)__half_as_ushort(a) | ((uint32_t)__half_as_ushort(b) << 16);
}
__device__ __forceinline__ void split1(float v, __nv_bfloat16& h, __nv_bfloat16& l) {
    h = __float2bfloat16(v);
    l = __float2bfloat16(v - __bfloat162float(h));
}

__global__ __launch_bounds__(256) void pack_x_kernel(
    const float* __restrict__ x0, const float* __restrict__ x1, const float* __restrict__ x2)
{
    size_t i = (size_t)blockIdx.x * 256 + threadIdx.x;   // float4 index
    if (i >= (size_t)NTOT * (DIN / 4)) return;
    int row = (int)(i >> 6);
    int c4  = (int)(i & 63);
    const float* src;
    if (row < N0C)            src = x0 + (size_t)row * DIN;
    else if (row < N0C + N1C) src = x1 + (size_t)(row - N0C) * DIN;
    else                      src = x2 + (size_t)(row - N0C - N1C) * DIN;
    float4 v = reinterpret_cast<const float4*>(src)[c4];
    __nv_bfloat16 h0,h1,h2,h3,l0,l1,l2,l3;
    split1(v.x,h0,l0); split1(v.y,h1,l1); split1(v.z,h2,l2); split1(v.w,h3,l3);
    reinterpret_cast<uint2*>(g_Xhi)[i] = make_uint2(pack2(h0,h1), pack2(h2,h3));
    reinterpret_cast<uint2*>(g_Xlo)[i] = make_uint2(pack2(l0,l1), pack2(l2,l3));
}

__global__ __launch_bounds__(256) void split_w1_kernel(const float* __restrict__ W1)
{
    int i = blockIdx.x * 256 + threadIdx.x;              // [h][n][k]
    if (i >= HEADS * DOUT * DIN) return;
    int h = i >> 15, n = (i >> 8) & 127, k = i & 255;
    float v = W1[(size_t)h * DIN * DOUT + (size_t)k * DOUT + n];
    __nv_bfloat16 hi, lo; split1(v, hi, lo);
    g_W1t_hi[i] = hi; g_W1t_lo[i] = lo;
}

__global__ __launch_bounds__(256) void split_wagg_kernel(const float* __restrict__ Wagg)
{
    int i = blockIdx.x * 256 + threadIdx.x;              // [h][n][k], k<512
    if (i >= HEADS * DOUT * 512) return;
    int h = i >> 16, n = (i >> 9) & 127, k = i & 511;
    float v = Wagg[(size_t)h * 512 * DOUT + (size_t)k * DOUT + n];
    __nv_bfloat16 hi, lo; split1(v, hi, lo);
    g_Waggt_hi[i] = hi; g_Waggt_lo[i] = lo;
}

__global__ __launch_bounds__(256) void zero_small_kernel()
{
    int i = blockIdx.x * 256 + threadIdx.x;
    if (i < HEADS * N0C)  g_a1[i] = 0.f;
    if (i < HEADS * NTOT) g_a2[i] = 0.f;
    if (i < 3 * N0C)      g_cnt[i] = 0;
}

// ---------------- CSR build ----------------------------------------------------
__global__ __launch_bounds__(256) void hist_kernel(const int* __restrict__ rows, int nnz, int lvl)
{
    int i = blockIdx.x * 256 + threadIdx.x;
    if (i < nnz) atomicAdd(&g_cnt[lvl * N0C + rows[i]], 1);
}

__global__ __launch_bounds__(1024) void scan_kernel()   // grid = 3
{
    const int lvl = blockIdx.x;
    const int* cnt = g_cnt + lvl * N0C;
    int* rp  = g_rowptr + lvl * (N0C + 1);
    int* pos = g_pos + lvl * N0C;
    __shared__ int ssum[1024];
    const int CH = (N0C + 1023) / 1024;   // 30
    int t = threadIdx.x;
    int base = t * CH;
    int s = 0;
    for (int k = 0; k < CH; k++) { int idx = base + k; if (idx < N0C) s += cnt[idx]; }
    ssum[t] = s; __syncthreads();
    for (int off = 1; off < 1024; off <<= 1) {
        int v = (t >= off) ? ssum[t - off] : 0;
        __syncthreads();
        ssum[t] += v;
        __syncthreads();
    }
    int run = (t == 0) ? 0 : ssum[t - 1];
    for (int k = 0; k < CH; k++) {
        int idx = base + k;
        if (idx < N0C) { rp[idx] = run; pos[idx] = run; run += cnt[idx]; }
    }
    if (t == 1023) rp[N0C] = run;
}

__global__ __launch_bounds__(256) void scatter_kernel(
    const int* __restrict__ rows, const int* __restrict__ cols,
    int nnz, int lvl, int ebase)
{
    int i = blockIdx.x * 256 + threadIdx.x;
    if (i >= nnz) return;
    int p = atomicAdd(&g_pos[lvl * N0C + rows[i]], 1);
    g_ecol[ebase + p] = cols[i];
}

// ---------------- shared MMA compute core --------------------------------------
__device__ __forceinline__ void compute_stage(uint32_t s0, int mwarp, int nwarp,
                                              int lane, float c[2][8][4])
{
    uint32_t ah[2][2][4], al[2][2][4];
#pragma unroll
    for (int i = 0; i < 2; i++)
#pragma unroll
        for (int kk = 0; kk < 2; kk++) {
            uint32_t off = swz((uint32_t)(mwarp + i * 16 + (lane & 15)),
                               (uint32_t)(kk * 2 + (lane >> 4)));
            ldsm4(ah[i][kk], s0 + off);
            ldsm4(al[i][kk], s0 + TILEB + off);
        }
#pragma unroll
    for (int j = 0; j < 4; j++) {
        uint32_t nrow = (uint32_t)(nwarp + j * 16 + ((lane >> 4) << 3) + (lane & 7));
        uint32_t csel = (uint32_t)((lane >> 3) & 1);
#pragma unroll
        for (int kk = 0; kk < 2; kk++) {
            uint32_t off = swz(nrow, (uint32_t)(kk * 2) + csel);
            uint32_t bh[4], bl[4];
            ldsm4(bh, s0 + 2 * TILEB + off);
            ldsm4(bl, s0 + 3 * TILEB + off);
#pragma unroll
            for (int i = 0; i < 2; i++) {
                mma16816(c[i][j * 2 + 0], ah[i][kk], bh);
                mma16816(c[i][j * 2 + 1], ah[i][kk], bh + 2);
                mma16816(c[i][j * 2 + 0], ah[i][kk], bl);
                mma16816(c[i][j * 2 + 1], ah[i][kk], bl + 2);
                mma16816(c[i][j * 2 + 0], al[i][kk], bh);
                mma16816(c[i][j * 2 + 1], al[i][kk], bh + 2);
            }
        }
    }
}

// ---------------- GEMM1: Y = relu(X@W1[h]+b1[h]) + fused a1/a2 partial dots ----
// grid = (HEADS, tiles): adjacent CTAs share the same A tile -> L2 reuse.
__global__ __launch_bounds__(256, 1) void gemm1_mma(
    const float* __restrict__ b1, const float* __restrict__ a1w,
    const float* __restrict__ a2w)
{
    extern __shared__ char smem[];
    __shared__ float sBias[128], sA1w[128], sA2w[128];
    uint32_t sb = smem_u32(smem);
    uint32_t tb = (sb + 1023u) & ~1023u;
    const int tid = threadIdx.x, lane = tid & 31, wid = tid >> 5;
    const int h = blockIdx.x, m0 = blockIdx.y * 128;
    const int mwarp = (wid & 3) * 32, nwarp = (wid >> 2) * 64;

    if (tid < 128) {
        sBias[tid] = b1[h * DOUT + tid];
        sA1w[tid]  = a1w[h * DOUT + tid];
        sA2w[tid]  = a2w[h * DOUT + tid];
    }

    float c[2][8][4];
#pragma unroll
    for (int i = 0; i < 2; i++)
#pragma unroll
        for (int j = 0; j < 8; j++)
#pragma unroll
            for (int q = 0; q < 4; q++) c[i][j][q] = 0.f;

    auto load = [&](int stage, int ks) {
        uint32_t s0 = tb + (uint32_t)stage * STAGEB;
        int k0 = ks * 32;
#pragma unroll
        for (int t = 0; t < 2; t++) {
            int idx = tid * 2 + t;
            int r = idx >> 2, cc = idx & 3;
            uint32_t dsw = swz((uint32_t)r, (uint32_t)cc);
            uint32_t n = (m0 + r < NTOT) ? 16u : 0u;
            size_t aoff = (size_t)(m0 + r) * DIN + k0 + cc * 8;
            size_t boff = ((size_t)h * DOUT + r) * DIN + k0 + cc * 8;
            cpa16(s0 + dsw,             g_Xhi    + aoff, n);
            cpa16(s0 + TILEB + dsw,     g_Xlo    + aoff, n);
            cpa16(s0 + 2 * TILEB + dsw, g_W1t_hi + boff, 16u);
            cpa16(s0 + 3 * TILEB + dsw, g_W1t_lo + boff, 16u);
        }
        cp_commit();
    };

    const int NKS = DIN / 32;   // 8
    load(0, 0);
    for (int ks = 0; ks < NKS; ks++) {
        if (ks + 1 < NKS) { load((ks + 1) & 1, ks + 1); cpwait1(); }
        else              { cpwait0(); }
        __syncthreads();
        compute_stage(tb + (uint32_t)(ks & 1) * STAGEB, mwarp, nwarp, lane, c);
        __syncthreads();
    }

    // epilogue: bias + relu; fp16 Y (all rows); bf16 hi/lo (rows<N0C); a1/a2 dots
#pragma unroll
    for (int i = 0; i < 2; i++) {
        int r0 = m0 + mwarp + i * 16 + (lane >> 2);
#pragma unroll
        for (int v = 0; v < 2; v++) {
            int row = r0 + v * 8;
            if (row >= NTOT) continue;
            size_t yfb = ((size_t)h * NTOT + row) * DOUT;
            bool lo_keep = (row < N0C);
            size_t yb = lo_keep ? ((size_t)h * N0C + row) * DOUT : 0;
            float p1 = 0.f, p2 = 0.f;
#pragma unroll
            for (int j = 0; j < 8; j++) {
                int col = nwarp + j * 8 + (lane & 3) * 2;
                float y0 = fmaxf(c[i][j][v * 2 + 0] + sBias[col], 0.f);
                float y1 = fmaxf(c[i][j][v * 2 + 1] + sBias[col + 1], 0.f);
                p1 = fmaf(y0, sA1w[col], p1); p1 = fmaf(y1, sA1w[col + 1], p1);
                p2 = fmaf(y0, sA2w[col], p2); p2 = fmaf(y1, sA2w[col + 1], p2);
                *reinterpret_cast<uint32_t*>(g_Yf16 + yfb + col) =
                    pack2h(__float2half_rn(y0), __float2half_rn(y1));
                if (lo_keep) {
                    __nv_bfloat16 h0, l0, h1, l1;
                    split1(y0, h0, l0); split1(y1, h1, l1);
                    *reinterpret_cast<uint32_t*>(g_Yhi + yb + col) = pack2(h0, h1);
                    *reinterpret_cast<uint32_t*>(g_Ylo + yb + col) = pack2(l0, l1);
                }
            }
            atomicAdd(&g_a2[h * NTOT + row], p2);
            if (lo_keep) atomicAdd(&g_a1[h * N0C + row], p1);
        }
    }
}

// ---------------- edge aggregation (CSR, register accumulate, 4-wide) ----------
// warp per (lvl, row), level-major; gridDim.y = head
__global__ __launch_bounds__(256) void edge_agg_kernel(
    const float* __restrict__ a1b, const float* __restrict__ a2b,
    int ebase1, int ebase2)
{
    int w = blockIdx.x * 8 + (threadIdx.x >> 5);
    if (w >= N0C * 3) return;
    const int h = blockIdx.y;
    const int lane = threadIdx.x & 31;
    int lvl = w / N0C;
    int row = w - lvl * N0C;

    int coff, eb;
    if (lvl == 0)      { coff = 0;          eb = 0; }
    else if (lvl == 1) { coff = N0C;        eb = ebase1; }
    else               { coff = N0C + N1C;  eb = ebase2; }

    int beg = g_rowptr[lvl * (N0C + 1) + row];
    int end = g_rowptr[lvl * (N0C + 1) + row + 1];

    const float a1r  = g_a1[h * N0C + row] + a1b[h] + a2b[h];
    const float* a2h = g_a2 + h * NTOT + coff;
    const __half* yh = g_Yf16 + ((size_t)h * NTOT + coff) * DOUT;
    const int* ec = g_ecol + eb;

    float ax = 0.f, ay = 0.f, az = 0.f, aw = 0.f;
    int e = beg;
    for (; e + 3 < end; e += 4) {
        int cc[4]; float t[4]; uint2 u[4];
#pragma unroll
        for (int j = 0; j < 4; j++) cc[j] = __ldg(ec + e + j);
#pragma unroll
        for (int j = 0; j < 4; j++) t[j] = a1r + __ldg(a2h + cc[j]);
#pragma unroll
        for (int j = 0; j < 4; j++)
            u[j] = *reinterpret_cast<const uint2*>(yh + (size_t)cc[j] * DOUT + lane * 4);
#pragma unroll
        for (int j = 0; j < 4; j++) {
            float att = __fdividef(1.f, 1.f + __expf(-t[j]));
            float2 f0 = __half22float2(*reinterpret_cast<__half2*>(&u[j].x));
            float2 f1 = __half22float2(*reinterpret_cast<__half2*>(&u[j].y));
            ax = fmaf(att, f0.x, ax); ay = fmaf(att, f0.y, ay);
            az = fmaf(att, f1.x, az); aw = fmaf(att, f1.y, aw);
        }
    }
    for (; e < end; e++) {
        int c0 = __ldg(ec + e);
        float t0 = a1r + __ldg(a2h + c0);
        uint2 u0 = *reinterpret_cast<const uint2*>(yh + (size_t)c0 * DOUT + lane * 4);
        float att0 = __fdividef(1.f, 1.f + __expf(-t0));
        float2 f0 = __half22float2(*reinterpret_cast<__half2*>(&u0.x));
        float2 f1 = __half22float2(*reinterpret_cast<__half2*>(&u0.y));
        ax = fmaf(att0, f0.x, ax); ay = fmaf(att0, f0.y, ay);
        az = fmaf(att0, f1.x, az); aw = fmaf(att0, f1.y, aw);
    }

    __nv_bfloat16 h0,h1,h2,h3,l0,l1,l2,l3;
    split1(ax,h0,l0); split1(ay,h1,l1); split1(az,h2,l2); split1(aw,h3,l3);
    size_t ob = (((size_t)h * 3 + lvl) * N0C + row) * DOUT + lane * 4;
    *reinterpret_cast<uint2*>(g_agghi + ob) = make_uint2(pack2(h0,h1), pack2(h2,h3));
    *reinterpret_cast<uint2*>(g_agglo + ob) = make_uint2(pack2(l0,l1), pack2(l2,l3));
}

// ---------------- GEMM2: out = mean_h(cat_h @ Wagg[h]) + mean bias --------------
__global__ __launch_bounds__(256, 1) void gemm2_mma(
    const float* __restrict__ bagg, float* __restrict__ out)
{
    extern __shared__ char smem[];
    __shared__ float sBsum[128];
    uint32_t sb = smem_u32(smem);
    uint32_t tb = (sb + 1023u) & ~1023u;
    const int tid = threadIdx.x, lane = tid & 31, wid = tid >> 5;
    const int m0 = blockIdx.x * 128;
    const int mwarp = (wid & 3) * 32, nwarp = (wid >> 2) * 64;

    if (tid < 128)
        sBsum[tid] = bagg[tid] + bagg[128 + tid] + bagg[256 + tid] + bagg[384 + tid];

    float c[2][8][4];
#pragma unroll
    for (int i = 0; i < 2; i++)
#pragma unroll
        for (int j = 0; j < 8; j++)
#pragma unroll
            for (int q = 0; q < 4; q++) c[i][j][q] = 0.f;

    auto load = [&](int stage, int ks) {
        uint32_t s0 = tb + (uint32_t)stage * STAGEB;
        int chunk = ks >> 2, inner = ks & 3;
        int h = chunk >> 2, part = chunk & 3;
        const __nv_bfloat16 *ah, *al;
        size_t abase;
        if (part == 0) {
            abase = ((size_t)h * N0C + m0) * DOUT;
            ah = g_Yhi; al = g_Ylo;
        } else {
            abase = ((size_t)(h * 3 + part - 1) * N0C + m0) * DOUT;
            ah = g_agghi; al = g_agglo;
        }
        size_t bbase = ((size_t)h * DOUT) * 512 + part * 128;
#pragma unroll
        for (int t = 0; t < 2; t++) {
            int idx = tid * 2 + t;
            int r = idx >> 2, cc = idx & 3;
            uint32_t dsw = swz((uint32_t)r, (uint32_t)cc);
            uint32_t n = (m0 + r < N0C) ? 16u : 0u;
            size_t aoff = abase + (size_t)r * DOUT + inner * 32 + cc * 8;
            size_t boff = bbase + (size_t)r * 512 + inner * 32 + cc * 8;
            cpa16(s0 + dsw,             ah + aoff, n);
            cpa16(s0 + TILEB + dsw,     al + aoff, n);
            cpa16(s0 + 2 * TILEB + dsw, g_Waggt_hi + boff, 16u);
            cpa16(s0 + 3 * TILEB + dsw, g_Waggt_lo + boff, 16u);
        }
        cp_commit();
    };

    const int NKS = 64;
    load(0, 0);
    for (int ks = 0; ks < NKS; ks++) {
        if (ks + 1 < NKS) { load((ks + 1) & 1, ks + 1); cpwait1(); }
        else              { cpwait0(); }
        __syncthreads();
        compute_stage(tb + (uint32_t)(ks & 1) * STAGEB, mwarp, nwarp, lane, c);
        __syncthreads();
    }

#pragma unroll
    for (int i = 0; i < 2; i++) {
        int r0 = m0 + mwarp + i * 16 + (lane >> 2);
#pragma unroll
        for (int v = 0; v < 2; v++) {
            int row = r0 + v * 8;
            if (row >= N0C) continue;
            float* dst = out + (size_t)row * DOUT;
#pragma unroll
            for (int j = 0; j < 8; j++) {
                int col = nwarp + j * 8 + (lane & 3) * 2;
                float v0 = 0.25f * (c[i][j][v * 2 + 0] + sBsum[col]);
                float v1 = 0.25f * (c[i][j][v * 2 + 1] + sBsum[col + 1]);
                *reinterpret_cast<float2*>(dst + col) = make_float2(v0, v1);
            }
        }
    }
}

// ---------------- launcher -------------------------------------------------------
extern "C" void kernel_launch(void* const* d_in, const int* in_sizes, int n_in,
                              void* d_out, int out_size)
{
    const float* x0    = (const float*)d_in[0];
    const float* x1    = (const float*)d_in[1];
    const float* x2    = (const float*)d_in[2];
    const int*   rows0 = (const int*)  d_in[3];
    const int*   cols0 = (const int*)  d_in[4];
    const int*   rows1 = (const int*)  d_in[5];
    const int*   cols1 = (const int*)  d_in[6];
    const int*   rows2 = (const int*)  d_in[7];
    const int*   cols2 = (const int*)  d_in[8];
    const float* W1    = (const float*)d_in[9];
    const float* b1    = (const float*)d_in[10];
    const float* a1w   = (const float*)d_in[11];
    const float* a1b   = (const float*)d_in[12];
    const float* a2w   = (const float*)d_in[13];
    const float* a2b   = (const float*)d_in[14];
    const float* Wagg  = (const float*)d_in[15];
    const float* bagg  = (const float*)d_in[16];
    float* out = (float*)d_out;

    const int nnz0 = in_sizes[3];
    const int nnz1 = in_sizes[5];
    const int nnz2 = in_sizes[7];

    static bool attr_done = false;
    if (!attr_done) {
        cudaFuncSetAttribute(gemm1_mma, cudaFuncAttributeMaxDynamicSharedMemorySize, GSMEM);
        cudaFuncSetAttribute(gemm2_mma, cudaFuncAttributeMaxDynamicSharedMemorySize, GSMEM);
        attr_done = true;
    }

    // 0) split inputs into bf16 hi/lo, zero small scratch
    pack_x_kernel<<<(NTOT * (DIN / 4) + 255) / 256, 256>>>(x0, x1, x2);
    split_w1_kernel<<<(HEADS * DOUT * DIN + 255) / 256, 256>>>(W1);
    split_wagg_kernel<<<(HEADS * DOUT * 512 + 255) / 256, 256>>>(Wagg);
    zero_small_kernel<<<(HEADS * NTOT + 255) / 256, 256>>>();

    // 1) CSR build (shared across heads)
    hist_kernel<<<(nnz0 + 255) / 256, 256>>>(rows0, nnz0, 0);
    hist_kernel<<<(nnz1 + 255) / 256, 256>>>(rows1, nnz1, 1);
    hist_kernel<<<(nnz2 + 255) / 256, 256>>>(rows2, nnz2, 2);
    scan_kernel<<<3, 1024>>>();
    scatter_kernel<<<(nnz0 + 255) / 256, 256>>>(rows0, cols0, nnz0, 0, 0);
    scatter_kernel<<<(nnz1 + 255) / 256, 256>>>(rows1, cols1, nnz1, 1, nnz0);
    scatter_kernel<<<(nnz2 + 255) / 256, 256>>>(rows2, cols2, nnz2, 2, nnz0 + nnz1);

    // 2) linear + relu for all levels (tensor cores), fused a1/a2 dots
    //    grid (HEADS, tiles): adjacent CTAs share the A tile via L2
    gemm1_mma<<<dim3(HEADS, (NTOT + 127) / 128), 256, GSMEM>>>(b1, a1w, a2w);

    // 3) attention-weighted aggregation (CSR, no atomics)
    edge_agg_kernel<<<dim3((N0C * 3 + 7) / 8, HEADS), 256>>>(a1b, a2b, nnz0, nnz0 + nnz1);

    // 4) concat + output projection + head mean (tensor cores)
    gemm2_mma<<<(N0C + 127) / 128, 256, GSMEM>>>(bagg, out);
}

// round 8
// speedup vs baseline: 2.5887x; 1.2151x over previous
#include <cuda_runtime.h>
#include <cuda_bf16.h>
#include <cuda_fp16.h>
#include <math.h>
#include <stdint.h>

#define N0C 30000
#define N1C 90000
#define N2C 60000
#define NTOT (N0C + N1C + N2C)   // 180000
#define DIN  256
#define DOUT 128
#define HEADS 4
#define EMAX 1320000

#define TILEB  8192u             // 128 rows x 32 bf16 (64B) = 8KB
#define STAGEB (4u * TILEB)      // Ahi, Alo, Bhi, Blo
#define GSMEM  (2u * STAGEB + 1024u)

// ---------------- scratch (device globals; no runtime allocation) ------------
__device__ __align__(128) __nv_bfloat16 g_Xhi[(size_t)NTOT * DIN];
__device__ __align__(128) __nv_bfloat16 g_Xlo[(size_t)NTOT * DIN];
__device__ __align__(128) __nv_bfloat16 g_W1t_hi[HEADS * DOUT * DIN];    // [h][n][k]
__device__ __align__(128) __nv_bfloat16 g_W1t_lo[HEADS * DOUT * DIN];
__device__ __align__(128) __nv_bfloat16 g_Waggt_hi[HEADS * DOUT * 512];  // [h][n][k]
__device__ __align__(128) __nv_bfloat16 g_Waggt_lo[HEADS * DOUT * 512];
__device__ __align__(128) __half        g_Yf16[(size_t)HEADS * NTOT * DOUT]; // all rows
__device__ __align__(128) __nv_bfloat16 g_Yhi[(size_t)HEADS * N0C * DOUT];   // rows<N0C
__device__ __align__(128) __nv_bfloat16 g_Ylo[(size_t)HEADS * N0C * DOUT];
__device__ __align__(128) float g_a1 [HEADS * N0C];
__device__ __align__(128) float g_a2 [HEADS * NTOT];
__device__ __align__(128) __nv_bfloat16 g_agghi[(size_t)HEADS * 3 * N0C * DOUT];
__device__ __align__(128) __nv_bfloat16 g_agglo[(size_t)HEADS * 3 * N0C * DOUT];
// CSR scratch
__device__ int g_cnt   [3 * N0C];
__device__ int g_rowptr[3 * (N0C + 1)];
__device__ int g_pos   [3 * N0C];
__device__ int g_ecol  [EMAX];

// ---------------- PTX helpers (all base-ISA) ----------------------------------
__device__ __forceinline__ uint32_t smem_u32(const void* p) {
    uint32_t a;
    asm("{ .reg .u64 t; cvta.to.shared.u64 t, %1; cvt.u32.u64 %0, t; }" : "=r"(a) : "l"(p));
    return a;
}
__device__ __forceinline__ void cpa16(uint32_t dst, const void* src, uint32_t n) {
    asm volatile("cp.async.cg.shared.global [%0], [%1], 16, %2;" :: "r"(dst), "l"(src), "r"(n));
}
__device__ __forceinline__ void cp_commit() { asm volatile("cp.async.commit_group;" ::: "memory"); }
__device__ __forceinline__ void cpwait1()  { asm volatile("cp.async.wait_group 1;" ::: "memory"); }
__device__ __forceinline__ void cpwait0()  { asm volatile("cp.async.wait_group 0;" ::: "memory"); }

__device__ __forceinline__ void ldsm4(uint32_t* r, uint32_t addr) {
    asm volatile("ldmatrix.sync.aligned.m8n8.x4.shared.b16 {%0,%1,%2,%3}, [%4];"
                 : "=r"(r[0]), "=r"(r[1]), "=r"(r[2]), "=r"(r[3]) : "r"(addr));
}
__device__ __forceinline__ void mma16816(float* c, const uint32_t* a, const uint32_t* b) {
    asm volatile("mma.sync.aligned.m16n8k16.row.col.f32.bf16.bf16.f32 "
                 "{%0,%1,%2,%3}, {%4,%5,%6,%7}, {%8,%9}, {%0,%1,%2,%3};"
                 : "+f"(c[0]), "+f"(c[1]), "+f"(c[2]), "+f"(c[3])
                 : "r"(a[0]), "r"(a[1]), "r"(a[2]), "r"(a[3]), "r"(b[0]), "r"(b[1]));
}
__device__ __forceinline__ uint32_t swz(uint32_t r, uint32_t c) {
    return r * 64u + ((c ^ ((r >> 1) & 3u)) << 4);
}

// ---------------- split / pack helpers ----------------------------------------
__device__ __forceinline__ uint32_t pack2(__nv_bfloat16 a, __nv_bfloat16 b) {
    return (uint32_t)__bfloat16_as_ushort(a) | ((uint32_t)__bfloat16_as_ushort(b) << 16);
}
__device__ __forceinline__ uint32_t pack2h(__half a, __half b) {
    return (uint32_t)__half_as_ushort(a) | ((uint32_t)__half_as_ushort(b) << 16);
}
__device__ __forceinline__ void split1(float v, __nv_bfloat16& h, __nv_bfloat16& l) {
    h = __float2bfloat16(v);
    l = __float2bfloat16(v - __bfloat162float(h));
}

__global__ __launch_bounds__(256) void pack_x_kernel(
    const float* __restrict__ x0, const float* __restrict__ x1, const float* __restrict__ x2)
{
    size_t i = (size_t)blockIdx.x * 256 + threadIdx.x;   // float4 index
    if (i >= (size_t)NTOT * (DIN / 4)) return;
    int row = (int)(i >> 6);
    int c4  = (int)(i & 63);
    const float* src;
    if (row < N0C)            src = x0 + (size_t)row * DIN;
    else if (row < N0C + N1C) src = x1 + (size_t)(row - N0C) * DIN;
    else                      src = x2 + (size_t)(row - N0C - N1C) * DIN;
    float4 v = reinterpret_cast<const float4*>(src)[c4];
    __nv_bfloat16 h0,h1,h2,h3,l0,l1,l2,l3;
    split1(v.x,h0,l0); split1(v.y,h1,l1); split1(v.z,h2,l2); split1(v.w,h3,l3);
    reinterpret_cast<uint2*>(g_Xhi)[i] = make_uint2(pack2(h0,h1), pack2(h2,h3));
    reinterpret_cast<uint2*>(g_Xlo)[i] = make_uint2(pack2(l0,l1), pack2(l2,l3));
}

__global__ __launch_bounds__(256) void split_w1_kernel(const float* __restrict__ W1)
{
    int i = blockIdx.x * 256 + threadIdx.x;              // [h][n][k]
    if (i >= HEADS * DOUT * DIN) return;
    int h = i >> 15, n = (i >> 8) & 127, k = i & 255;
    float v = W1[(size_t)h * DIN * DOUT + (size_t)k * DOUT + n];
    __nv_bfloat16 hi, lo; split1(v, hi, lo);
    g_W1t_hi[i] = hi; g_W1t_lo[i] = lo;
}

__global__ __launch_bounds__(256) void split_wagg_kernel(const float* __restrict__ Wagg)
{
    int i = blockIdx.x * 256 + threadIdx.x;              // [h][n][k], k<512
    if (i >= HEADS * DOUT * 512) return;
    int h = i >> 16, n = (i >> 9) & 127, k = i & 511;
    float v = Wagg[(size_t)h * 512 * DOUT + (size_t)k * DOUT + n];
    __nv_bfloat16 hi, lo; split1(v, hi, lo);
    g_Waggt_hi[i] = hi; g_Waggt_lo[i] = lo;
}

__global__ __launch_bounds__(256) void zero_small_kernel()
{
    int i = blockIdx.x * 256 + threadIdx.x;
    if (i < HEADS * N0C)  g_a1[i] = 0.f;
    if (i < HEADS * NTOT) g_a2[i] = 0.f;
    if (i < 3 * N0C)      g_cnt[i] = 0;
}

// ---------------- CSR build ----------------------------------------------------
__global__ __launch_bounds__(256) void hist_kernel(const int* __restrict__ rows, int nnz, int lvl)
{
    int i = blockIdx.x * 256 + threadIdx.x;
    if (i < nnz) atomicAdd(&g_cnt[lvl * N0C + rows[i]], 1);
}

__global__ __launch_bounds__(1024) void scan_kernel()   // grid = 3
{
    const int lvl = blockIdx.x;
    const int* cnt = g_cnt + lvl * N0C;
    int* rp  = g_rowptr + lvl * (N0C + 1);
    int* pos = g_pos + lvl * N0C;
    __shared__ int ssum[1024];
    const int CH = (N0C + 1023) / 1024;   // 30
    int t = threadIdx.x;
    int base = t * CH;
    int s = 0;
    for (int k = 0; k < CH; k++) { int idx = base + k; if (idx < N0C) s += cnt[idx]; }
    ssum[t] = s; __syncthreads();
    for (int off = 1; off < 1024; off <<= 1) {
        int v = (t >= off) ? ssum[t - off] : 0;
        __syncthreads();
        ssum[t] += v;
        __syncthreads();
    }
    int run = (t == 0) ? 0 : ssum[t - 1];
    for (int k = 0; k < CH; k++) {
        int idx = base + k;
        if (idx < N0C) { rp[idx] = run; pos[idx] = run; run += cnt[idx]; }
    }
    if (t == 1023) rp[N0C] = run;
}

__global__ __launch_bounds__(256) void scatter_kernel(
    const int* __restrict__ rows, const int* __restrict__ cols,
    int nnz, int lvl, int ebase)
{
    int i = blockIdx.x * 256 + threadIdx.x;
    if (i >= nnz) return;
    int p = atomicAdd(&g_pos[lvl * N0C + rows[i]], 1);
    g_ecol[ebase + p] = cols[i];
}

// ---------------- shared MMA compute core --------------------------------------
__device__ __forceinline__ void compute_stage(uint32_t s0, int mwarp, int nwarp,
                                              int lane, float c[2][8][4])
{
    uint32_t ah[2][2][4], al[2][2][4];
#pragma unroll
    for (int i = 0; i < 2; i++)
#pragma unroll
        for (int kk = 0; kk < 2; kk++) {
            uint32_t off = swz((uint32_t)(mwarp + i * 16 + (lane & 15)),
                               (uint32_t)(kk * 2 + (lane >> 4)));
            ldsm4(ah[i][kk], s0 + off);
            ldsm4(al[i][kk], s0 + TILEB + off);
        }
#pragma unroll
    for (int j = 0; j < 4; j++) {
        uint32_t nrow = (uint32_t)(nwarp + j * 16 + ((lane >> 4) << 3) + (lane & 7));
        uint32_t csel = (uint32_t)((lane >> 3) & 1);
#pragma unroll
        for (int kk = 0; kk < 2; kk++) {
            uint32_t off = swz(nrow, (uint32_t)(kk * 2) + csel);
            uint32_t bh[4], bl[4];
            ldsm4(bh, s0 + 2 * TILEB + off);
            ldsm4(bl, s0 + 3 * TILEB + off);
#pragma unroll
            for (int i = 0; i < 2; i++) {
                mma16816(c[i][j * 2 + 0], ah[i][kk], bh);
                mma16816(c[i][j * 2 + 1], ah[i][kk], bh + 2);
                mma16816(c[i][j * 2 + 0], ah[i][kk], bl);
                mma16816(c[i][j * 2 + 1], ah[i][kk], bl + 2);
                mma16816(c[i][j * 2 + 0], al[i][kk], bh);
                mma16816(c[i][j * 2 + 1], al[i][kk], bh + 2);
            }
        }
    }
}

// ---------------- GEMM1: Y = relu(X@W1[h]+b1[h]) + fused a1/a2 partial dots ----
// grid = (HEADS, tiles); occ target 2 CTAs/SM.
__global__ __launch_bounds__(256, 2) void gemm1_mma(
    const float* __restrict__ b1, const float* __restrict__ a1w,
    const float* __restrict__ a2w)
{
    extern __shared__ char smem[];
    __shared__ float sBias[128], sA1w[128], sA2w[128];
    uint32_t sb = smem_u32(smem);
    uint32_t tb = (sb + 1023u) & ~1023u;
    const int tid = threadIdx.x, lane = tid & 31, wid = tid >> 5;
    const int h = blockIdx.x, m0 = blockIdx.y * 128;
    const int mwarp = (wid & 3) * 32, nwarp = (wid >> 2) * 64;

    if (tid < 128) {
        sBias[tid] = b1[h * DOUT + tid];
        sA1w[tid]  = a1w[h * DOUT + tid];
        sA2w[tid]  = a2w[h * DOUT + tid];
    }

    float c[2][8][4];
#pragma unroll
    for (int i = 0; i < 2; i++)
#pragma unroll
        for (int j = 0; j < 8; j++)
#pragma unroll
            for (int q = 0; q < 4; q++) c[i][j][q] = 0.f;

    auto load = [&](int stage, int ks) {
        uint32_t s0 = tb + (uint32_t)stage * STAGEB;
        int k0 = ks * 32;
#pragma unroll
        for (int t = 0; t < 2; t++) {
            int idx = tid * 2 + t;
            int r = idx >> 2, cc = idx & 3;
            uint32_t dsw = swz((uint32_t)r, (uint32_t)cc);
            uint32_t n = (m0 + r < NTOT) ? 16u : 0u;
            size_t aoff = (size_t)(m0 + r) * DIN + k0 + cc * 8;
            size_t boff = ((size_t)h * DOUT + r) * DIN + k0 + cc * 8;
            cpa16(s0 + dsw,             g_Xhi    + aoff, n);
            cpa16(s0 + TILEB + dsw,     g_Xlo    + aoff, n);
            cpa16(s0 + 2 * TILEB + dsw, g_W1t_hi + boff, 16u);
            cpa16(s0 + 3 * TILEB + dsw, g_W1t_lo + boff, 16u);
        }
        cp_commit();
    };

    const int NKS = DIN / 32;   // 8
    load(0, 0);
    for (int ks = 0; ks < NKS; ks++) {
        if (ks + 1 < NKS) { load((ks + 1) & 1, ks + 1); cpwait1(); }
        else              { cpwait0(); }
        __syncthreads();
        compute_stage(tb + (uint32_t)(ks & 1) * STAGEB, mwarp, nwarp, lane, c);
        __syncthreads();
    }

    // epilogue
#pragma unroll
    for (int i = 0; i < 2; i++) {
        int r0 = m0 + mwarp + i * 16 + (lane >> 2);
#pragma unroll
        for (int v = 0; v < 2; v++) {
            int row = r0 + v * 8;
            if (row >= NTOT) continue;
            size_t yfb = ((size_t)h * NTOT + row) * DOUT;
            bool lo_keep = (row < N0C);
            size_t yb = lo_keep ? ((size_t)h * N0C + row) * DOUT : 0;
            float p1 = 0.f, p2 = 0.f;
#pragma unroll
            for (int j = 0; j < 8; j++) {
                int col = nwarp + j * 8 + (lane & 3) * 2;
                float y0 = fmaxf(c[i][j][v * 2 + 0] + sBias[col], 0.f);
                float y1 = fmaxf(c[i][j][v * 2 + 1] + sBias[col + 1], 0.f);
                p1 = fmaf(y0, sA1w[col], p1); p1 = fmaf(y1, sA1w[col + 1], p1);
                p2 = fmaf(y0, sA2w[col], p2); p2 = fmaf(y1, sA2w[col + 1], p2);
                *reinterpret_cast<uint32_t*>(g_Yf16 + yfb + col) =
                    pack2h(__float2half_rn(y0), __float2half_rn(y1));
                if (lo_keep) {
                    __nv_bfloat16 h0, l0, h1, l1;
                    split1(y0, h0, l0); split1(y1, h1, l1);
                    *reinterpret_cast<uint32_t*>(g_Yhi + yb + col) = pack2(h0, h1);
                    *reinterpret_cast<uint32_t*>(g_Ylo + yb + col) = pack2(l0, l1);
                }
            }
            atomicAdd(&g_a2[h * NTOT + row], p2);
            if (lo_keep) atomicAdd(&g_a1[h * N0C + row], p1);
        }
    }
}

// ---------------- edge aggregation (CSR, register accumulate, 4-wide) ----------
__global__ __launch_bounds__(256) void edge_agg_kernel(
    const float* __restrict__ a1b, const float* __restrict__ a2b,
    int ebase1, int ebase2)
{
    int w = blockIdx.x * 8 + (threadIdx.x >> 5);
    if (w >= N0C * 3) return;
    const int h = blockIdx.y;
    const int lane = threadIdx.x & 31;
    int lvl = w / N0C;
    int row = w - lvl * N0C;

    int coff, eb;
    if (lvl == 0)      { coff = 0;          eb = 0; }
    else if (lvl == 1) { coff = N0C;        eb = ebase1; }
    else               { coff = N0C + N1C;  eb = ebase2; }

    int beg = g_rowptr[lvl * (N0C + 1) + row];
    int end = g_rowptr[lvl * (N0C + 1) + row + 1];

    const float a1r  = g_a1[h * N0C + row] + a1b[h] + a2b[h];
    const float* a2h = g_a2 + h * NTOT + coff;
    const __half* yh = g_Yf16 + ((size_t)h * NTOT + coff) * DOUT;
    const int* ec = g_ecol + eb;

    float ax = 0.f, ay = 0.f, az = 0.f, aw = 0.f;
    int e = beg;
    for (; e + 3 < end; e += 4) {
        int cc[4]; float t[4]; uint2 u[4];
#pragma unroll
        for (int j = 0; j < 4; j++) cc[j] = __ldg(ec + e + j);
#pragma unroll
        for (int j = 0; j < 4; j++) t[j] = a1r + __ldg(a2h + cc[j]);
#pragma unroll
        for (int j = 0; j < 4; j++)
            u[j] = *reinterpret_cast<const uint2*>(yh + (size_t)cc[j] * DOUT + lane * 4);
#pragma unroll
        for (int j = 0; j < 4; j++) {
            float att = __fdividef(1.f, 1.f + __expf(-t[j]));
            float2 f0 = __half22float2(*reinterpret_cast<__half2*>(&u[j].x));
            float2 f1 = __half22float2(*reinterpret_cast<__half2*>(&u[j].y));
            ax = fmaf(att, f0.x, ax); ay = fmaf(att, f0.y, ay);
            az = fmaf(att, f1.x, az); aw = fmaf(att, f1.y, aw);
        }
    }
    for (; e < end; e++) {
        int c0 = __ldg(ec + e);
        float t0 = a1r + __ldg(a2h + c0);
        uint2 u0 = *reinterpret_cast<const uint2*>(yh + (size_t)c0 * DOUT + lane * 4);
        float att0 = __fdividef(1.f, 1.f + __expf(-t0));
        float2 f0 = __half22float2(*reinterpret_cast<__half2*>(&u0.x));
        float2 f1 = __half22float2(*reinterpret_cast<__half2*>(&u0.y));
        ax = fmaf(att0, f0.x, ax); ay = fmaf(att0, f0.y, ay);
        az = fmaf(att0, f1.x, az); aw = fmaf(att0, f1.y, aw);
    }

    __nv_bfloat16 h0,h1,h2,h3,l0,l1,l2,l3;
    split1(ax,h0,l0); split1(ay,h1,l1); split1(az,h2,l2); split1(aw,h3,l3);
    size_t ob = (((size_t)h * 3 + lvl) * N0C + row) * DOUT + lane * 4;
    *reinterpret_cast<uint2*>(g_agghi + ob) = make_uint2(pack2(h0,h1), pack2(h2,h3));
    *reinterpret_cast<uint2*>(g_agglo + ob) = make_uint2(pack2(l0,l1), pack2(l2,l3));
}

// ---------------- GEMM2: out = mean_h(cat_h @ Wagg[h]) + mean bias --------------
__global__ __launch_bounds__(256, 2) void gemm2_mma(
    const float* __restrict__ bagg, float* __restrict__ out)
{
    extern __shared__ char smem[];
    __shared__ float sBsum[128];
    uint32_t sb = smem_u32(smem);
    uint32_t tb = (sb + 1023u) & ~1023u;
    const int tid = threadIdx.x, lane = tid & 31, wid = tid >> 5;
    const int m0 = blockIdx.x * 128;
    const int mwarp = (wid & 3) * 32, nwarp = (wid >> 2) * 64;

    if (tid < 128)
        sBsum[tid] = bagg[tid] + bagg[128 + tid] + bagg[256 + tid] + bagg[384 + tid];

    float c[2][8][4];
#pragma unroll
    for (int i = 0; i < 2; i++)
#pragma unroll
        for (int j = 0; j < 8; j++)
#pragma unroll
            for (int q = 0; q < 4; q++) c[i][j][q] = 0.f;

    auto load = [&](int stage, int ks) {
        uint32_t s0 = tb + (uint32_t)stage * STAGEB;
        int chunk = ks >> 2, inner = ks & 3;
        int h = chunk >> 2, part = chunk & 3;
        const __nv_bfloat16 *ah, *al;
        size_t abase;
        if (part == 0) {
            abase = ((size_t)h * N0C + m0) * DOUT;
            ah = g_Yhi; al = g_Ylo;
        } else {
            abase = ((size_t)(h * 3 + part - 1) * N0C + m0) * DOUT;
            ah = g_agghi; al = g_agglo;
        }
        size_t bbase = ((size_t)h * DOUT) * 512 + part * 128;
#pragma unroll
        for (int t = 0; t < 2; t++) {
            int idx = tid * 2 + t;
            int r = idx >> 2, cc = idx & 3;
            uint32_t dsw = swz((uint32_t)r, (uint32_t)cc);
            uint32_t n = (m0 + r < N0C) ? 16u : 0u;
            size_t aoff = abase + (size_t)r * DOUT + inner * 32 + cc * 8;
            size_t boff = bbase + (size_t)r * 512 + inner * 32 + cc * 8;
            cpa16(s0 + dsw,             ah + aoff, n);
            cpa16(s0 + TILEB + dsw,     al + aoff, n);
            cpa16(s0 + 2 * TILEB + dsw, g_Waggt_hi + boff, 16u);
            cpa16(s0 + 3 * TILEB + dsw, g_Waggt_lo + boff, 16u);
        }
        cp_commit();
    };

    const int NKS = 64;
    load(0, 0);
    for (int ks = 0; ks < NKS; ks++) {
        if (ks + 1 < NKS) { load((ks + 1) & 1, ks + 1); cpwait1(); }
        else              { cpwait0(); }
        __syncthreads();
        compute_stage(tb + (uint32_t)(ks & 1) * STAGEB, mwarp, nwarp, lane, c);
        __syncthreads();
    }

#pragma unroll
    for (int i = 0; i < 2; i++) {
        int r0 = m0 + mwarp + i * 16 + (lane >> 2);
#pragma unroll
        for (int v = 0; v < 2; v++) {
            int row = r0 + v * 8;
            if (row >= N0C) continue;
            float* dst = out + (size_t)row * DOUT;
#pragma unroll
            for (int j = 0; j < 8; j++) {
                int col = nwarp + j * 8 + (lane & 3) * 2;
                float v0 = 0.25f * (c[i][j][v * 2 + 0] + sBsum[col]);
                float v1 = 0.25f * (c[i][j][v * 2 + 1] + sBsum[col + 1]);
                *reinterpret_cast<float2*>(dst + col) = make_float2(v0, v1);
            }
        }
    }
}

// ---------------- launcher -------------------------------------------------------
extern "C" void kernel_launch(void* const* d_in, const int* in_sizes, int n_in,
                              void* d_out, int out_size)
{
    const float* x0    = (const float*)d_in[0];
    const float* x1    = (const float*)d_in[1];
    const float* x2    = (const float*)d_in[2];
    const int*   rows0 = (const int*)  d_in[3];
    const int*   cols0 = (const int*)  d_in[4];
    const int*   rows1 = (const int*)  d_in[5];
    const int*   cols1 = (const int*)  d_in[6];
    const int*   rows2 = (const int*)  d_in[7];
    const int*   cols2 = (const int*)  d_in[8];
    const float* W1    = (const float*)d_in[9];
    const float* b1    = (const float*)d_in[10];
    const float* a1w   = (const float*)d_in[11];
    const float* a1b   = (const float*)d_in[12];
    const float* a2w   = (const float*)d_in[13];
    const float* a2b   = (const float*)d_in[14];
    const float* Wagg  = (const float*)d_in[15];
    const float* bagg  = (const float*)d_in[16];
    float* out = (float*)d_out;

    const int nnz0 = in_sizes[3];
    const int nnz1 = in_sizes[5];
    const int nnz2 = in_sizes[7];

    static bool init_done = false;
    static cudaStream_t s2;
    static cudaEvent_t evFork, evJoin;
    if (!init_done) {
        cudaFuncSetAttribute(gemm1_mma, cudaFuncAttributeMaxDynamicSharedMemorySize, GSMEM);
        cudaFuncSetAttribute(gemm2_mma, cudaFuncAttributeMaxDynamicSharedMemorySize, GSMEM);
        cudaStreamCreateWithFlags(&s2, cudaStreamNonBlocking);
        cudaEventCreateWithFlags(&evFork, cudaEventDisableTiming);
        cudaEventCreateWithFlags(&evJoin, cudaEventDisableTiming);
        init_done = true;
    }

    // 0) zero (feeds both branches)
    zero_small_kernel<<<(HEADS * NTOT + 255) / 256, 256>>>();

    // fork: CSR build on side stream, concurrent with pack/split/gemm1
    cudaEventRecord(evFork, 0);
    cudaStreamWaitEvent(s2, evFork, 0);
    hist_kernel<<<(nnz0 + 255) / 256, 256, 0, s2>>>(rows0, nnz0, 0);
    hist_kernel<<<(nnz1 + 255) / 256, 256, 0, s2>>>(rows1, nnz1, 1);
    hist_kernel<<<(nnz2 + 255) / 256, 256, 0, s2>>>(rows2, nnz2, 2);
    scan_kernel<<<3, 1024, 0, s2>>>();
    scatter_kernel<<<(nnz0 + 255) / 256, 256, 0, s2>>>(rows0, cols0, nnz0, 0, 0);
    scatter_kernel<<<(nnz1 + 255) / 256, 256, 0, s2>>>(rows1, cols1, nnz1, 1, nnz0);
    scatter_kernel<<<(nnz2 + 255) / 256, 256, 0, s2>>>(rows2, cols2, nnz2, 2, nnz0 + nnz1);
    cudaEventRecord(evJoin, s2);

    // main branch: split inputs, gemm1
    pack_x_kernel<<<(NTOT * (DIN / 4) + 255) / 256, 256>>>(x0, x1, x2);
    split_w1_kernel<<<(HEADS * DOUT * DIN + 255) / 256, 256>>>(W1);
    split_wagg_kernel<<<(HEADS * DOUT * 512 + 255) / 256, 256>>>(Wagg);
    gemm1_mma<<<dim3(HEADS, (NTOT + 127) / 128), 256, GSMEM>>>(b1, a1w, a2w);

    // join, then edge aggregation + output GEMM
    cudaStreamWaitEvent(0, evJoin, 0);
    edge_agg_kernel<<<dim3((N0C * 3 + 7) / 8, HEADS), 256>>>(a1b, a2b, nnz0, nnz0 + nnz1);
    gemm2_mma<<<(N0C + 127) / 128, 256, GSMEM>>>(bagg, out);
}